// round 1
// baseline (speedup 1.0000x reference)
#include <cuda_runtime.h>
#include <math.h>

#define NN   20000
#define EE   320000
#define TT   16
#define PP   4096
#define DIN  128
#define HH   256
#define DDm  512
#define FFD  2048
#define TPR  (TT*PP)   // 65536

// ---------------- scratch (static device globals; no allocation) ----------------
__device__ float g_deg[NN];
__device__ float g_agg[NN*HH];
__device__ float g_h1 [NN*HH];
__device__ float g_h2 [NN*HH];
__device__ float g_h   [(size_t)TPR*DDm];
__device__ float g_q   [(size_t)TPR*DDm];
__device__ float g_k   [(size_t)TPR*DDm];
__device__ float g_v   [(size_t)TPR*DDm];
__device__ float g_o   [(size_t)TPR*DDm];
__device__ float g_proj[(size_t)TPR*DDm];
__device__ float g_ff  [(size_t)TPR*FFD];

// ---------------- tiny utility kernels ----------------
__global__ void k_zero(float* __restrict__ p, int n4) {
    int i = blockIdx.x * blockDim.x + threadIdx.x;
    if (i < n4) ((float4*)p)[i] = make_float4(0.f, 0.f, 0.f, 0.f);
}

__global__ void k_deg(const int* __restrict__ dst) {
    int e = blockIdx.x * blockDim.x + threadIdx.x;
    if (e < EE) atomicAdd(&g_deg[dst[e]], 1.0f);
}

// scatter-mean: agg[dst] += x[src] / max(deg[dst],1). F = 4<<lg features.
__global__ void k_scatter(const float* __restrict__ x, const int* __restrict__ src,
                          const int* __restrict__ dst, int lg) {
    int i  = blockIdx.x * blockDim.x + threadIdx.x;
    int e  = i >> lg;
    if (e >= EE) return;
    int F4 = 1 << lg;
    int c4 = i & (F4 - 1);
    int s = src[e], d = dst[e];
    float invd = 1.0f / fmaxf(g_deg[d], 1.0f);
    float4 xv = ((const float4*)x)[(size_t)s * F4 + c4];
    float* ap = g_agg + ((size_t)d * F4 + c4) * 4;
    atomicAdd(ap + 0, xv.x * invd);
    atomicAdd(ap + 1, xv.y * invd);
    atomicAdd(ap + 2, xv.z * invd);
    atomicAdd(ap + 3, xv.w * invd);
}

// ---------------- fp32 tiled GEMM: C = A1@W1 + A2@W2 + bias (opt ReLU) ----------------
// BM=BN=128, BK=16, 256 threads, 8x8 per-thread tile. N % 128 == 0, K % 16 == 0 required.
template<bool RELU>
__global__ void __launch_bounds__(256)
gemm_dual(const float* __restrict__ A1, const float* __restrict__ W1, int K1,
          const float* __restrict__ A2, const float* __restrict__ W2, int K2,
          const float* __restrict__ bias, float* __restrict__ C, int M, int N) {
    __shared__ float As[16][132];
    __shared__ float Bs[16][128];
    int tid  = threadIdx.x;
    int bRow = blockIdx.y * 128;
    int bCol = blockIdx.x * 128;
    int tCol = tid & 15, tRow = tid >> 4;

    float acc[8][8];
#pragma unroll
    for (int i = 0; i < 8; i++)
#pragma unroll
        for (int j = 0; j < 8; j++) acc[i][j] = 0.f;

    for (int phase = 0; phase < 2; phase++) {
        const float* A = phase ? A2 : A1;
        const float* W = phase ? W2 : W1;
        int K = phase ? K2 : K1;
        if (A == nullptr || K == 0) continue;
        for (int k0 = 0; k0 < K; k0 += 16) {
            // A tile -> As[k][m] (transposed)
#pragma unroll
            for (int r = 0; r < 2; r++) {
                int li = tid + r * 256;
                int m = li >> 2, kq = li & 3;
                float4 v = make_float4(0.f, 0.f, 0.f, 0.f);
                if (bRow + m < M)
                    v = *(const float4*)(A + (size_t)(bRow + m) * K + k0 + kq * 4);
                As[kq * 4 + 0][m] = v.x;
                As[kq * 4 + 1][m] = v.y;
                As[kq * 4 + 2][m] = v.z;
                As[kq * 4 + 3][m] = v.w;
            }
            // B tile -> Bs[k][n]
#pragma unroll
            for (int r = 0; r < 2; r++) {
                int li = tid + r * 256;
                int k = li >> 5, nq = li & 31;
                *(float4*)&Bs[k][nq * 4] =
                    *(const float4*)(W + (size_t)(k0 + k) * N + bCol + nq * 4);
            }
            __syncthreads();
#pragma unroll
            for (int kk = 0; kk < 16; kk++) {
                float a[8], b[8];
                *(float4*)(a)     = *(float4*)&As[kk][tRow * 8];
                *(float4*)(a + 4) = *(float4*)&As[kk][tRow * 8 + 4];
                *(float4*)(b)     = *(float4*)&Bs[kk][tCol * 8];
                *(float4*)(b + 4) = *(float4*)&Bs[kk][tCol * 8 + 4];
#pragma unroll
                for (int i = 0; i < 8; i++)
#pragma unroll
                    for (int j = 0; j < 8; j++) acc[i][j] += a[i] * b[j];
            }
            __syncthreads();
        }
    }
    // epilogue
#pragma unroll
    for (int i = 0; i < 8; i++) {
        int row = bRow + tRow * 8 + i;
        if (row >= M) break;
        float* crow = C + (size_t)row * N + bCol + tCol * 8;
#pragma unroll
        for (int j = 0; j < 8; j += 4) {
            float4 v;
            v.x = acc[i][j + 0] + bias[bCol + tCol * 8 + j + 0];
            v.y = acc[i][j + 1] + bias[bCol + tCol * 8 + j + 1];
            v.z = acc[i][j + 2] + bias[bCol + tCol * 8 + j + 2];
            v.w = acc[i][j + 3] + bias[bCol + tCol * 8 + j + 3];
            if (RELU) {
                v.x = fmaxf(v.x, 0.f); v.y = fmaxf(v.y, 0.f);
                v.z = fmaxf(v.z, 0.f); v.w = fmaxf(v.w, 0.f);
            }
            *(float4*)(crow + j) = v;
        }
    }
}

// ---------------- row L2-normalize of g_h2 (H=256), warp per row ----------------
__global__ void k_l2norm() {
    int w = threadIdx.x >> 5, lane = threadIdx.x & 31;
    int row = blockIdx.x * 8 + w;
    if (row >= NN) return;
    float* p = g_h2 + (size_t)row * HH;
    float v[8]; float ss = 0.f;
#pragma unroll
    for (int i = 0; i < 8; i++) { v[i] = p[lane + i * 32]; ss += v[i] * v[i]; }
#pragma unroll
    for (int o = 16; o; o >>= 1) ss += __shfl_xor_sync(0xffffffffu, ss, o);
    float inv = 1.0f / fmaxf(sqrtf(ss), 1e-12f);
#pragma unroll
    for (int i = 0; i < 8; i++) p[lane + i * 32] = v[i] * inv;
}

// gather h2[idx[p]] into att_in half (d_out) and the residual-stream buffer g_h
__global__ void k_gather(const int* __restrict__ idx, float* __restrict__ att_out,
                         int t, int off) {
    int i = blockIdx.x * blockDim.x + threadIdx.x;
    if (i >= PP * HH) return;
    int p = i >> 8, c = i & 255;
    int n = idx[p];
    float val = g_h2[(size_t)n * HH + c];
    size_t o = ((size_t)(t * PP + p)) * DDm + off + c;
    att_out[o] = val;
    g_h[o] = val;
}

// ---------------- banded attention (T=16, window 4), block per (p, head), 64 threads ----
__global__ void k_attn() {
    int p = blockIdx.x, h = blockIdx.y;
    int tid = threadIdx.x;  // 64
    __shared__ float qs[TT][64], ks[TT][64], vs[TT][64];
    __shared__ float att[TT][4];
    size_t base = (size_t)p * DDm + h * 64 + tid;
#pragma unroll
    for (int t = 0; t < TT; t++) {
        size_t off = (size_t)t * PP * DDm + base;
        qs[t][tid] = g_q[off];
        ks[t][tid] = g_k[off];
        vs[t][tid] = g_v[off];
    }
    __syncthreads();
    {
        int t = tid >> 2, j = tid & 3, s = t - j;
        float sc = -INFINITY;
        if (s >= 0) {
            float a = 0.f;
#pragma unroll
            for (int d = 0; d < 64; d++) a += qs[t][d] * ks[s][d];
            sc = a * 0.125f;  // 1/sqrt(64)
        }
        att[t][j] = sc;
    }
    __syncthreads();
    if (tid < TT) {
        float m = -INFINITY;
#pragma unroll
        for (int j = 0; j < 4; j++) m = fmaxf(m, att[tid][j]);
        float sum = 0.f, e[4];
#pragma unroll
        for (int j = 0; j < 4; j++) {
            float x = att[tid][j];
            float ee = (x == -INFINITY) ? 0.f : expf(x - m);
            e[j] = ee; sum += ee;
        }
        float inv = 1.0f / sum;
#pragma unroll
        for (int j = 0; j < 4; j++) att[tid][j] = e[j] * inv;
    }
    __syncthreads();
#pragma unroll
    for (int t = 0; t < TT; t++) {
        float a = 0.f;
#pragma unroll
        for (int j = 0; j < 4; j++) {
            int s = t - j;
            if (s >= 0) a += att[t][j] * vs[s][tid];
        }
        g_o[(size_t)t * PP * DDm + base] = a;
    }
}

// ---------------- LayerNorm over D=512: h = LN(h + r)*g + b, warp per row ----------------
__global__ void k_ln(const float* __restrict__ r, const float* __restrict__ g,
                     const float* __restrict__ b) {
    int w = threadIdx.x >> 5, lane = threadIdx.x & 31;
    size_t row = (size_t)blockIdx.x * 8 + w;
    float* xr = g_h + row * DDm;
    const float* rr = r + row * DDm;
    float v[16]; float s = 0.f;
#pragma unroll
    for (int i = 0; i < 16; i++) {
        int c = lane + i * 32;
        float t = xr[c] + rr[c];
        v[i] = t; s += t;
    }
#pragma unroll
    for (int o = 16; o; o >>= 1) s += __shfl_xor_sync(0xffffffffu, s, o);
    float mean = s * (1.0f / DDm);
    float vs = 0.f;
#pragma unroll
    for (int i = 0; i < 16; i++) { float d = v[i] - mean; vs += d * d; }
#pragma unroll
    for (int o = 16; o; o >>= 1) vs += __shfl_xor_sync(0xffffffffu, vs, o);
    float inv = rsqrtf(vs * (1.0f / DDm) + 1e-5f);
#pragma unroll
    for (int i = 0; i < 16; i++) {
        int c = lane + i * 32;
        xr[c] = (v[i] - mean) * inv * g[c] + b[c];
    }
}

// ---------------- final head: out[row] = h[row] . W_out ----------------
__global__ void k_out(const float* __restrict__ wout, float* __restrict__ out) {
    int w = threadIdx.x >> 5, lane = threadIdx.x & 31;
    size_t row = (size_t)blockIdx.x * 8 + w;
    const float* hr = g_h + row * DDm;
    float s = 0.f;
#pragma unroll
    for (int i = 0; i < 16; i++) { int c = lane + i * 32; s += hr[c] * wout[c]; }
#pragma unroll
    for (int o = 16; o; o >>= 1) s += __shfl_xor_sync(0xffffffffu, s, o);
    if (lane == 0) out[row] = s;
}

// =======================================================================================
extern "C" void kernel_launch(void* const* d_in, const int* in_sizes, int n_in,
                              void* d_out, int out_size) {
    const float* x_i  = (const float*)d_in[0];
    const float* x_j  = (const float*)d_in[1];
    const int* src_i  = (const int*)d_in[2];
    const int* dst_i  = (const int*)d_in[3];
    const int* src_j  = (const int*)d_in[4];
    const int* dst_j  = (const int*)d_in[5];
    const int* idx_i  = (const int*)d_in[6];
    const int* idx_j  = (const int*)d_in[7];
    const float* W1s  = (const float*)d_in[8];
    const float* W1n  = (const float*)d_in[9];
    const float* b1   = (const float*)d_in[10];
    const float* W2s  = (const float*)d_in[11];
    const float* W2n  = (const float*)d_in[12];
    const float* b2   = (const float*)d_in[13];
    const float* Wq   = (const float*)d_in[14];
    const float* Wk   = (const float*)d_in[15];
    const float* Wv   = (const float*)d_in[16];
    const float* bq   = (const float*)d_in[17];
    const float* bk   = (const float*)d_in[18];
    const float* bv   = (const float*)d_in[19];
    const float* Wo   = (const float*)d_in[20];
    const float* bo   = (const float*)d_in[21];
    const float* Wf1  = (const float*)d_in[22];
    const float* bf1  = (const float*)d_in[23];
    const float* Wf2  = (const float*)d_in[24];
    const float* bf2  = (const float*)d_in[25];
    const float* g1   = (const float*)d_in[26];
    const float* bg1  = (const float*)d_in[27];
    const float* g2   = (const float*)d_in[28];
    const float* bg2  = (const float*)d_in[29];
    const float* Wout = (const float*)d_in[30];
    float* out = (float*)d_out;

    float *p_deg, *p_agg, *p_h1, *p_h2, *p_h, *p_q, *p_k, *p_v, *p_o, *p_proj, *p_ff;
    cudaGetSymbolAddress((void**)&p_deg,  g_deg);
    cudaGetSymbolAddress((void**)&p_agg,  g_agg);
    cudaGetSymbolAddress((void**)&p_h1,   g_h1);
    cudaGetSymbolAddress((void**)&p_h2,   g_h2);
    cudaGetSymbolAddress((void**)&p_h,    g_h);
    cudaGetSymbolAddress((void**)&p_q,    g_q);
    cudaGetSymbolAddress((void**)&p_k,    g_k);
    cudaGetSymbolAddress((void**)&p_v,    g_v);
    cudaGetSymbolAddress((void**)&p_o,    g_o);
    cudaGetSymbolAddress((void**)&p_proj, g_proj);
    cudaGetSymbolAddress((void**)&p_ff,   g_ff);

    // ---------- GraphSAGE over T timesteps x 2 graphs ----------
    for (int t = 0; t < TT; t++) {
        for (int gsel = 0; gsel < 2; gsel++) {
            const float* x  = (gsel ? x_j  : x_i ) + (size_t)t * NN * DIN;
            const int* src  = (gsel ? src_j: src_i) + (size_t)t * EE;
            const int* dstp = (gsel ? dst_j: dst_i) + (size_t)t * EE;
            const int* idx  = (gsel ? idx_j: idx_i) + (size_t)t * PP;

            k_zero<<<(NN/4 + 255)/256, 256>>>(p_deg, NN/4);
            k_deg <<<(EE + 255)/256, 256>>>(dstp);

            // layer 1: agg over x (F=128)
            k_zero   <<<(NN*DIN/4 + 255)/256, 256>>>(p_agg, NN*DIN/4);
            k_scatter<<<(EE*(DIN/4) + 255)/256, 256>>>(x, src, dstp, 5);
            gemm_dual<true><<<dim3(HH/128, (NN + 127)/128), 256>>>(
                x, W1s, DIN, p_agg, W1n, DIN, b1, p_h1, NN, HH);

            // layer 2: agg over h1 (F=256)
            k_zero   <<<(NN*HH/4 + 255)/256, 256>>>(p_agg, NN*HH/4);
            k_scatter<<<(EE*(HH/4) + 255)/256, 256>>>(p_h1, src, dstp, 6);
            gemm_dual<false><<<dim3(HH/128, (NN + 127)/128), 256>>>(
                p_h1, W2s, HH, p_agg, W2n, HH, b2, p_h2, NN, HH);

            k_l2norm<<<(NN + 7)/8, 256>>>();
            k_gather<<<(PP*HH + 255)/256, 256>>>(idx, out, t, gsel * HH);
        }
    }

    // ---------- transformer (L=2) ----------
    for (int l = 0; l < 2; l++) {
        const float* wq = Wq + (size_t)l * DDm * DDm;
        const float* wk = Wk + (size_t)l * DDm * DDm;
        const float* wv = Wv + (size_t)l * DDm * DDm;
        const float* wo = Wo + (size_t)l * DDm * DDm;
        const float* wf1 = Wf1 + (size_t)l * DDm * FFD;
        const float* wf2 = Wf2 + (size_t)l * FFD * DDm;

        gemm_dual<false><<<dim3(DDm/128, TPR/128), 256>>>(
            p_h, wq, DDm, nullptr, nullptr, 0, bq + l*DDm, p_q, TPR, DDm);
        gemm_dual<false><<<dim3(DDm/128, TPR/128), 256>>>(
            p_h, wk, DDm, nullptr, nullptr, 0, bk + l*DDm, p_k, TPR, DDm);
        gemm_dual<false><<<dim3(DDm/128, TPR/128), 256>>>(
            p_h, wv, DDm, nullptr, nullptr, 0, bv + l*DDm, p_v, TPR, DDm);

        k_attn<<<dim3(PP, 8), 64>>>();

        gemm_dual<false><<<dim3(DDm/128, TPR/128), 256>>>(
            p_o, wo, DDm, nullptr, nullptr, 0, bo + l*DDm, p_proj, TPR, DDm);
        k_ln<<<TPR/8, 256>>>(p_proj, g1 + l*DDm, bg1 + l*DDm);

        gemm_dual<true><<<dim3(FFD/128, TPR/128), 256>>>(
            p_h, wf1, DDm, nullptr, nullptr, 0, bf1 + l*FFD, p_ff, TPR, FFD);
        gemm_dual<false><<<dim3(DDm/128, TPR/128), 256>>>(
            p_ff, wf2, FFD, nullptr, nullptr, 0, bf2 + l*DDm, p_proj, TPR, DDm);
        k_ln<<<TPR/8, 256>>>(p_proj, g2 + l*DDm, bg2 + l*DDm);
    }

    k_out<<<TPR/8, 256>>>(Wout, out + (size_t)TPR * DDm);
}

// round 3
// speedup vs baseline: 1.6812x; 1.6812x over previous
#include <cuda_runtime.h>
#include <cuda_bf16.h>
#include <math.h>
#include <stdint.h>

#define NN   20000
#define EE   320000
#define TT   16
#define PP   4096
#define DIN  128
#define HH   256
#define DDm  512
#define FFD  2048
#define TPR  (TT*PP)   // 65536

// ---------------- scratch (static device globals; no allocation) ----------------
__device__ float g_deg[NN];
__device__ float g_agg[NN*HH];
__device__ float g_h1 [NN*HH];
__device__ float g_h2 [NN*HH];
__device__ float g_h   [(size_t)TPR*DDm];
__device__ float g_q   [(size_t)TPR*DDm];
__device__ float g_k   [(size_t)TPR*DDm];
__device__ float g_v   [(size_t)TPR*DDm];
__device__ float g_o   [(size_t)TPR*DDm];
__device__ float g_proj[(size_t)TPR*DDm];
__device__ float g_ff  [(size_t)TPR*FFD];
__device__ __nv_bfloat16 g_w[12976128];

// ---------------- helpers ----------------
__device__ __forceinline__ uint32_t smem_u32(const void* p) {
    uint32_t a;
    asm("{ .reg .u64 t; cvta.to.shared.u64 t, %1; cvt.u32.u64 %0, t; }" : "=r"(a) : "l"(p));
    return a;
}
__device__ __forceinline__ void ldsm4(uint32_t* r, uint32_t addr) {
    asm volatile("ldmatrix.sync.aligned.m8n8.x4.shared.b16 {%0,%1,%2,%3}, [%4];"
                 : "=r"(r[0]), "=r"(r[1]), "=r"(r[2]), "=r"(r[3]) : "r"(addr));
}
__device__ __forceinline__ void mma16816(float* c, const uint32_t* a, const uint32_t* b) {
    asm volatile("mma.sync.aligned.m16n8k16.row.col.f32.bf16.bf16.f32 "
                 "{%0,%1,%2,%3}, {%4,%5,%6,%7}, {%8,%9}, {%0,%1,%2,%3};"
                 : "+f"(c[0]), "+f"(c[1]), "+f"(c[2]), "+f"(c[3])
                 : "r"(a[0]), "r"(a[1]), "r"(a[2]), "r"(a[3]), "r"(b[0]), "r"(b[1]));
}
__device__ __forceinline__ uint32_t pack2(float a, float b) {
    __nv_bfloat162 t = __floats2bfloat162_rn(a, b);
    return *reinterpret_cast<uint32_t*>(&t);
}

// smem geometry: rows of 32 bf16 padded to 80 bytes (conflict-free ldmatrix)
#define RSTR  80
#define MATB  (128*RSTR)   // 10240 bytes per matrix tile
#define BUFB  (4*MATB)     // Ah, Al, Bh, Bl
#define GSMEM (2*BUFB)     // double buffered = 81920

// ---------------- HMMA GEMM: C = A1@W1 (+ A2@W2) + bias, opt ReLU ----------------
// A fp32 [M][K]; W pre-transposed bf16 hi/lo [N][K]. BM=BN=128, BK=32.
// bf16x3 compensation: Ah*Bh + Ah*Bl + Al*Bh, fp32 accum.
template<bool RELU>
__global__ void __launch_bounds__(256)
gemm_mma(const float* __restrict__ A1, const __nv_bfloat16* __restrict__ B1h,
         const __nv_bfloat16* __restrict__ B1l, int K1,
         const float* __restrict__ A2, const __nv_bfloat16* __restrict__ B2h,
         const __nv_bfloat16* __restrict__ B2l, int K2,
         const float* __restrict__ bias, float* __restrict__ C, int M, int N) {
    extern __shared__ char smb[];
    const uint32_t sb = smem_u32(smb);
    const int tid = threadIdx.x, lane = tid & 31, wid = tid >> 5;
    const int bRow = blockIdx.y * 128, bCol = blockIdx.x * 128;
    const int wm = wid & 3, wn = wid >> 2;          // warp tile (wm*32, wn*64)
    const int lrow = tid >> 1, lhalf = tid & 1;     // staging: row 0..127, half 0..1

    const int nc1 = K1 >> 5;
    const int nc  = nc1 + (K2 >> 5);

    float acc[2][8][4];
#pragma unroll
    for (int i = 0; i < 2; i++)
#pragma unroll
        for (int j = 0; j < 8; j++)
#pragma unroll
            for (int q = 0; q < 4; q++) acc[i][j][q] = 0.f;

    float a_st[16];
    uint4 bh_st[2], bl_st[2];

#define GLOAD(cc) do {                                                          \
    const float* A_; const __nv_bfloat16 *Bh_, *Bl_; int K_, k0_;               \
    if ((cc) < nc1) { A_ = A1; Bh_ = B1h; Bl_ = B1l; K_ = K1; k0_ = (cc) << 5; }\
    else { A_ = A2; Bh_ = B2h; Bl_ = B2l; K_ = K2; k0_ = ((cc) - nc1) << 5; }   \
    const int grow_ = bRow + lrow;                                              \
    if (grow_ < M) {                                                            \
        const float* ap_ = A_ + (size_t)grow_ * K_ + k0_ + lhalf * 16;          \
        *(float4*)(a_st + 0)  = ((const float4*)ap_)[0];                        \
        *(float4*)(a_st + 4)  = ((const float4*)ap_)[1];                        \
        *(float4*)(a_st + 8)  = ((const float4*)ap_)[2];                        \
        *(float4*)(a_st + 12) = ((const float4*)ap_)[3];                        \
    } else {                                                                    \
        _Pragma("unroll") for (int j_ = 0; j_ < 16; j_++) a_st[j_] = 0.f;       \
    }                                                                           \
    const size_t bo_ = (size_t)(bCol + lrow) * K_ + k0_ + lhalf * 16;           \
    bh_st[0] = ((const uint4*)(Bh_ + bo_))[0];                                  \
    bh_st[1] = ((const uint4*)(Bh_ + bo_))[1];                                  \
    bl_st[0] = ((const uint4*)(Bl_ + bo_))[0];                                  \
    bl_st[1] = ((const uint4*)(Bl_ + bo_))[1];                                  \
} while (0)

#define SSTORE(buf) do {                                                        \
    char* base_ = smb + (buf) * BUFB;                                          \
    const uint32_t ro_ = lrow * RSTR + lhalf * 32;                              \
    uint32_t hi_[8], lo_[8];                                                    \
    _Pragma("unroll") for (int j_ = 0; j_ < 8; j_++) {                          \
        float f0_ = a_st[2*j_], f1_ = a_st[2*j_+1];                             \
        __nv_bfloat16 h0_ = __float2bfloat16(f0_), h1_ = __float2bfloat16(f1_); \
        float v0_ = __bfloat162float(h0_), v1_ = __bfloat162float(h1_);         \
        hi_[j_] = pack2(v0_, v1_);                                              \
        lo_[j_] = pack2(f0_ - v0_, f1_ - v1_);                                  \
    }                                                                           \
    *(uint4*)(base_ + ro_)             = make_uint4(hi_[0],hi_[1],hi_[2],hi_[3]);\
    *(uint4*)(base_ + ro_ + 16)        = make_uint4(hi_[4],hi_[5],hi_[6],hi_[7]);\
    *(uint4*)(base_ + MATB + ro_)      = make_uint4(lo_[0],lo_[1],lo_[2],lo_[3]);\
    *(uint4*)(base_ + MATB + ro_ + 16) = make_uint4(lo_[4],lo_[5],lo_[6],lo_[7]);\
    *(uint4*)(base_ + 2*MATB + ro_)      = bh_st[0];                            \
    *(uint4*)(base_ + 2*MATB + ro_ + 16) = bh_st[1];                            \
    *(uint4*)(base_ + 3*MATB + ro_)      = bl_st[0];                            \
    *(uint4*)(base_ + 3*MATB + ro_ + 16) = bl_st[1];                            \
} while (0)

#define COMPUTE(buf) do {                                                       \
    const uint32_t ah_ = sb + (buf) * BUFB;                                     \
    const uint32_t al_ = ah_ + MATB, bhp_ = ah_ + 2*MATB, blp_ = ah_ + 3*MATB;  \
    _Pragma("unroll") for (int ks_ = 0; ks_ < 2; ks_++) {                       \
        uint32_t aH_[2][4], aL_[2][4], bH_[4][4], bL_[4][4];                    \
        const int arow_ = wm * 32 + (lane & 15);                                \
        const int acol_ = ks_ * 32 + ((lane >> 4) << 4);                        \
        ldsm4(aH_[0], ah_ + arow_ * RSTR + acol_);                              \
        ldsm4(aH_[1], ah_ + (arow_ + 16) * RSTR + acol_);                       \
        ldsm4(aL_[0], al_ + arow_ * RSTR + acol_);                              \
        ldsm4(aL_[1], al_ + (arow_ + 16) * RSTR + acol_);                       \
        const int br_ = lane & 7, bg_ = lane >> 3;                              \
        const int brow_ = wn * 64 + ((bg_ >> 1) << 3) + br_;                    \
        const int bcol_ = ks_ * 32 + ((bg_ & 1) << 4);                          \
        _Pragma("unroll") for (int nj_ = 0; nj_ < 4; nj_++) {                   \
            ldsm4(bH_[nj_], bhp_ + (brow_ + nj_ * 16) * RSTR + bcol_);          \
            ldsm4(bL_[nj_], blp_ + (brow_ + nj_ * 16) * RSTR + bcol_);          \
        }                                                                       \
        _Pragma("unroll") for (int mi_ = 0; mi_ < 2; mi_++)                     \
        _Pragma("unroll") for (int ni_ = 0; ni_ < 8; ni_++) {                   \
            const uint32_t* bh2_ = &bH_[ni_ >> 1][(ni_ & 1) * 2];               \
            const uint32_t* bl2_ = &bL_[ni_ >> 1][(ni_ & 1) * 2];               \
            mma16816(acc[mi_][ni_], aH_[mi_], bh2_);                            \
            mma16816(acc[mi_][ni_], aH_[mi_], bl2_);                            \
            mma16816(acc[mi_][ni_], aL_[mi_], bh2_);                            \
        }                                                                       \
    }                                                                           \
} while (0)

    GLOAD(0);
    SSTORE(0);
    __syncthreads();
    for (int c = 0; c < nc; c++) {
        if (c + 1 < nc) GLOAD(c + 1);
        COMPUTE(c & 1);
        if (c + 1 < nc) SSTORE((c + 1) & 1);
        __syncthreads();
    }

    // epilogue
#pragma unroll
    for (int mi = 0; mi < 2; mi++) {
        const int r0 = bRow + wm * 32 + mi * 16 + (lane >> 2);
#pragma unroll
        for (int ni = 0; ni < 8; ni++) {
            const int col = bCol + wn * 64 + ni * 8 + (lane & 3) * 2;
            const float b0 = bias[col], b1 = bias[col + 1];
            if (r0 < M) {
                float c0 = acc[mi][ni][0] + b0, c1 = acc[mi][ni][1] + b1;
                if (RELU) { c0 = fmaxf(c0, 0.f); c1 = fmaxf(c1, 0.f); }
                *(float2*)(C + (size_t)r0 * N + col) = make_float2(c0, c1);
            }
            if (r0 + 8 < M) {
                float c2 = acc[mi][ni][2] + b0, c3 = acc[mi][ni][3] + b1;
                if (RELU) { c2 = fmaxf(c2, 0.f); c3 = fmaxf(c3, 0.f); }
                *(float2*)(C + (size_t)(r0 + 8) * N + col) = make_float2(c2, c3);
            }
        }
    }
#undef GLOAD
#undef SSTORE
#undef COMPUTE
}

// ---------------- weight prep: W[K][N] fp32 -> Th/Tl [N][K] bf16 ----------------
__global__ void k_wprep(const float* __restrict__ W, __nv_bfloat16* __restrict__ Th,
                        __nv_bfloat16* __restrict__ Tl, int K, int N) {
    __shared__ float s[32][33];
    int n0 = blockIdx.x * 32, k0 = blockIdx.y * 32;
    for (int r = threadIdx.y; r < 32; r += 8)
        s[r][threadIdx.x] = W[(size_t)(k0 + r) * N + n0 + threadIdx.x];
    __syncthreads();
    for (int r = threadIdx.y; r < 32; r += 8) {
        float f = s[threadIdx.x][r];
        __nv_bfloat16 hb = __float2bfloat16(f);
        float hv = __bfloat162float(hb);
        size_t o = (size_t)(n0 + r) * K + k0 + threadIdx.x;
        Th[o] = hb;
        Tl[o] = __float2bfloat16(f - hv);
    }
}

// ---------------- utility kernels ----------------
__global__ void k_zero(float* __restrict__ p, int n4) {
    int i = blockIdx.x * blockDim.x + threadIdx.x;
    if (i < n4) ((float4*)p)[i] = make_float4(0.f, 0.f, 0.f, 0.f);
}
__global__ void k_deg(const int* __restrict__ dst) {
    int e = blockIdx.x * blockDim.x + threadIdx.x;
    if (e < EE) atomicAdd(&g_deg[dst[e]], 1.0f);
}
__global__ void k_scatter(const float* __restrict__ x, const int* __restrict__ src,
                          const int* __restrict__ dst, int lg) {
    int i  = blockIdx.x * blockDim.x + threadIdx.x;
    int e  = i >> lg;
    if (e >= EE) return;
    int F4 = 1 << lg;
    int c4 = i & (F4 - 1);
    int s = src[e], d = dst[e];
    float invd = 1.0f / fmaxf(g_deg[d], 1.0f);
    float4 xv = ((const float4*)x)[(size_t)s * F4 + c4];
    float* ap = g_agg + ((size_t)d * F4 + c4) * 4;
    atomicAdd(ap + 0, xv.x * invd);
    atomicAdd(ap + 1, xv.y * invd);
    atomicAdd(ap + 2, xv.z * invd);
    atomicAdd(ap + 3, xv.w * invd);
}
__global__ void k_l2norm() {
    int w = threadIdx.x >> 5, lane = threadIdx.x & 31;
    int row = blockIdx.x * 8 + w;
    if (row >= NN) return;
    float* p = g_h2 + (size_t)row * HH;
    float v[8]; float ss = 0.f;
#pragma unroll
    for (int i = 0; i < 8; i++) { v[i] = p[lane + i * 32]; ss += v[i] * v[i]; }
#pragma unroll
    for (int o = 16; o; o >>= 1) ss += __shfl_xor_sync(0xffffffffu, ss, o);
    float inv = 1.0f / fmaxf(sqrtf(ss), 1e-12f);
#pragma unroll
    for (int i = 0; i < 8; i++) p[lane + i * 32] = v[i] * inv;
}
__global__ void k_gather(const int* __restrict__ idx, float* __restrict__ att_out,
                         int t, int off) {
    int i = blockIdx.x * blockDim.x + threadIdx.x;
    if (i >= PP * HH) return;
    int p = i >> 8, c = i & 255;
    int n = idx[p];
    float val = g_h2[(size_t)n * HH + c];
    size_t o = ((size_t)(t * PP + p)) * DDm + off + c;
    att_out[o] = val;
    g_h[o] = val;
}
__global__ void k_attn() {
    int p = blockIdx.x, h = blockIdx.y;
    int tid = threadIdx.x;
    __shared__ float qs[TT][64], ks[TT][64], vs[TT][64];
    __shared__ float att[TT][4];
    size_t base = (size_t)p * DDm + h * 64 + tid;
#pragma unroll
    for (int t = 0; t < TT; t++) {
        size_t off = (size_t)t * PP * DDm + base;
        qs[t][tid] = g_q[off];
        ks[t][tid] = g_k[off];
        vs[t][tid] = g_v[off];
    }
    __syncthreads();
    {
        int t = tid >> 2, j = tid & 3, s = t - j;
        float sc = -INFINITY;
        if (s >= 0) {
            float a = 0.f;
#pragma unroll
            for (int d = 0; d < 64; d++) a += qs[t][d] * ks[s][d];
            sc = a * 0.125f;
        }
        att[t][j] = sc;
    }
    __syncthreads();
    if (tid < TT) {
        float m = -INFINITY;
#pragma unroll
        for (int j = 0; j < 4; j++) m = fmaxf(m, att[tid][j]);
        float sum = 0.f, e[4];
#pragma unroll
        for (int j = 0; j < 4; j++) {
            float x = att[tid][j];
            float ee = (x == -INFINITY) ? 0.f : expf(x - m);
            e[j] = ee; sum += ee;
        }
        float inv = 1.0f / sum;
#pragma unroll
        for (int j = 0; j < 4; j++) att[tid][j] = e[j] * inv;
    }
    __syncthreads();
#pragma unroll
    for (int t = 0; t < TT; t++) {
        float a = 0.f;
#pragma unroll
        for (int j = 0; j < 4; j++) {
            int s = t - j;
            if (s >= 0) a += att[t][j] * vs[s][tid];
        }
        g_o[(size_t)t * PP * DDm + base] = a;
    }
}
__global__ void k_ln(const float* __restrict__ r, const float* __restrict__ g,
                     const float* __restrict__ b) {
    int w = threadIdx.x >> 5, lane = threadIdx.x & 31;
    size_t row = (size_t)blockIdx.x * 8 + w;
    float* xr = g_h + row * DDm;
    const float* rr = r + row * DDm;
    float v[16]; float s = 0.f;
#pragma unroll
    for (int i = 0; i < 16; i++) {
        int c = lane + i * 32;
        float t = xr[c] + rr[c];
        v[i] = t; s += t;
    }
#pragma unroll
    for (int o = 16; o; o >>= 1) s += __shfl_xor_sync(0xffffffffu, s, o);
    float mean = s * (1.0f / DDm);
    float vs = 0.f;
#pragma unroll
    for (int i = 0; i < 16; i++) { float d = v[i] - mean; vs += d * d; }
#pragma unroll
    for (int o = 16; o; o >>= 1) vs += __shfl_xor_sync(0xffffffffu, vs, o);
    float inv = rsqrtf(vs * (1.0f / DDm) + 1e-5f);
#pragma unroll
    for (int i = 0; i < 16; i++) {
        int c = lane + i * 32;
        xr[c] = (v[i] - mean) * inv * g[c] + b[c];
    }
}
__global__ void k_out(const float* __restrict__ wout, float* __restrict__ out) {
    int w = threadIdx.x >> 5, lane = threadIdx.x & 31;
    size_t row = (size_t)blockIdx.x * 8 + w;
    const float* hr = g_h + row * DDm;
    float s = 0.f;
#pragma unroll
    for (int i = 0; i < 16; i++) { int c = lane + i * 32; s += hr[c] * wout[c]; }
#pragma unroll
    for (int o = 16; o; o >>= 1) s += __shfl_xor_sync(0xffffffffu, s, o);
    if (lane == 0) out[row] = s;
}

// =======================================================================================
extern "C" void kernel_launch(void* const* d_in, const int* in_sizes, int n_in,
                              void* d_out, int out_size) {
    const float* x_i  = (const float*)d_in[0];
    const float* x_j  = (const float*)d_in[1];
    const int* src_i  = (const int*)d_in[2];
    const int* dst_i  = (const int*)d_in[3];
    const int* src_j  = (const int*)d_in[4];
    const int* dst_j  = (const int*)d_in[5];
    const int* idx_i  = (const int*)d_in[6];
    const int* idx_j  = (const int*)d_in[7];
    const float* W1s  = (const float*)d_in[8];
    const float* W1n  = (const float*)d_in[9];
    const float* b1   = (const float*)d_in[10];
    const float* W2s  = (const float*)d_in[11];
    const float* W2n  = (const float*)d_in[12];
    const float* b2   = (const float*)d_in[13];
    const float* Wq   = (const float*)d_in[14];
    const float* Wk   = (const float*)d_in[15];
    const float* Wv   = (const float*)d_in[16];
    const float* bq   = (const float*)d_in[17];
    const float* bk   = (const float*)d_in[18];
    const float* bv   = (const float*)d_in[19];
    const float* Wo   = (const float*)d_in[20];
    const float* bo   = (const float*)d_in[21];
    const float* Wf1  = (const float*)d_in[22];
    const float* bf1  = (const float*)d_in[23];
    const float* Wf2  = (const float*)d_in[24];
    const float* bf2  = (const float*)d_in[25];
    const float* g1   = (const float*)d_in[26];
    const float* bg1  = (const float*)d_in[27];
    const float* g2   = (const float*)d_in[28];
    const float* bg2  = (const float*)d_in[29];
    const float* Wout = (const float*)d_in[30];
    float* out = (float*)d_out;

    float *p_agg, *p_h1, *p_h2, *p_deg, *p_h, *p_q, *p_k, *p_v, *p_o, *p_proj, *p_ff;
    __nv_bfloat16* p_w;
    cudaGetSymbolAddress((void**)&p_deg,  g_deg);
    cudaGetSymbolAddress((void**)&p_agg,  g_agg);
    cudaGetSymbolAddress((void**)&p_h1,   g_h1);
    cudaGetSymbolAddress((void**)&p_h2,   g_h2);
    cudaGetSymbolAddress((void**)&p_h,    g_h);
    cudaGetSymbolAddress((void**)&p_q,    g_q);
    cudaGetSymbolAddress((void**)&p_k,    g_k);
    cudaGetSymbolAddress((void**)&p_v,    g_v);
    cudaGetSymbolAddress((void**)&p_o,    g_o);
    cudaGetSymbolAddress((void**)&p_proj, g_proj);
    cudaGetSymbolAddress((void**)&p_ff,   g_ff);
    cudaGetSymbolAddress((void**)&p_w,    g_w);

    cudaFuncSetAttribute(gemm_mma<false>, cudaFuncAttributeMaxDynamicSharedMemorySize, GSMEM);
    cudaFuncSetAttribute(gemm_mma<true>,  cudaFuncAttributeMaxDynamicSharedMemorySize, GSMEM);

    size_t off = 0;
    auto prep = [&](const float* W, int K, int N) -> size_t {
        size_t b = off;
        k_wprep<<<dim3(N/32, K/32), dim3(32, 8)>>>(W, p_w + b, p_w + b + (size_t)K*N, K, N);
        off += 2 * (size_t)K * N;
        return b;
    };
    size_t oW1s = prep(W1s, DIN, HH), oW1n = prep(W1n, DIN, HH);
    size_t oW2s = prep(W2s, HH, HH),  oW2n = prep(W2n, HH, HH);
    size_t oWq[2], oWk[2], oWv[2], oWo[2], oWf1[2], oWf2[2];
    for (int l = 0; l < 2; l++) {
        oWq[l]  = prep(Wq  + (size_t)l*DDm*DDm, DDm, DDm);
        oWk[l]  = prep(Wk  + (size_t)l*DDm*DDm, DDm, DDm);
        oWv[l]  = prep(Wv  + (size_t)l*DDm*DDm, DDm, DDm);
        oWo[l]  = prep(Wo  + (size_t)l*DDm*DDm, DDm, DDm);
        oWf1[l] = prep(Wf1 + (size_t)l*DDm*FFD, DDm, FFD);
        oWf2[l] = prep(Wf2 + (size_t)l*FFD*DDm, FFD, DDm);
    }
    auto BH = [&](size_t b) { return p_w + b; };
    auto BL = [&](size_t b, size_t K, size_t N) { return p_w + b + K * N; };

    for (int t = 0; t < TT; t++) {
        for (int gsel = 0; gsel < 2; gsel++) {
            const float* x  = (gsel ? x_j  : x_i ) + (size_t)t * NN * DIN;
            const int* src  = (gsel ? src_j: src_i) + (size_t)t * EE;
            const int* dstp = (gsel ? dst_j: dst_i) + (size_t)t * EE;
            const int* idx  = (gsel ? idx_j: idx_i) + (size_t)t * PP;

            k_zero<<<(NN/4 + 255)/256, 256>>>(p_deg, NN/4);
            k_deg <<<(EE + 255)/256, 256>>>(dstp);

            k_zero   <<<(NN*DIN/4 + 255)/256, 256>>>(p_agg, NN*DIN/4);
            k_scatter<<<(EE*(DIN/4) + 255)/256, 256>>>(x, src, dstp, 5);
            gemm_mma<true><<<dim3(HH/128, (NN + 127)/128), 256, GSMEM>>>(
                x, BH(oW1s), BL(oW1s, DIN, HH), DIN,
                p_agg, BH(oW1n), BL(oW1n, DIN, HH), DIN, b1, p_h1, NN, HH);

            k_zero   <<<(NN*HH/4 + 255)/256, 256>>>(p_agg, NN*HH/4);
            k_scatter<<<(EE*(HH/4) + 255)/256, 256>>>(p_h1, src, dstp, 6);
            gemm_mma<false><<<dim3(HH/128, (NN + 127)/128), 256, GSMEM>>>(
                p_h1, BH(oW2s), BL(oW2s, HH, HH), HH,
                p_agg, BH(oW2n), BL(oW2n, HH, HH), HH, b2, p_h2, NN, HH);

            k_l2norm<<<(NN + 7)/8, 256>>>();
            k_gather<<<(PP*HH + 255)/256, 256>>>(idx, out, t, gsel * HH);
        }
    }

    for (int l = 0; l < 2; l++) {
        gemm_mma<false><<<dim3(DDm/128, TPR/128), 256, GSMEM>>>(
            p_h, BH(oWq[l]), BL(oWq[l], DDm, DDm), DDm,
            nullptr, nullptr, nullptr, 0, bq + l*DDm, p_q, TPR, DDm);
        gemm_mma<false><<<dim3(DDm/128, TPR/128), 256, GSMEM>>>(
            p_h, BH(oWk[l]), BL(oWk[l], DDm, DDm), DDm,
            nullptr, nullptr, nullptr, 0, bk + l*DDm, p_k, TPR, DDm);
        gemm_mma<false><<<dim3(DDm/128, TPR/128), 256, GSMEM>>>(
            p_h, BH(oWv[l]), BL(oWv[l], DDm, DDm), DDm,
            nullptr, nullptr, nullptr, 0, bv + l*DDm, p_v, TPR, DDm);

        k_attn<<<dim3(PP, 8), 64>>>();

        gemm_mma<false><<<dim3(DDm/128, TPR/128), 256, GSMEM>>>(
            p_o, BH(oWo[l]), BL(oWo[l], DDm, DDm), DDm,
            nullptr, nullptr, nullptr, 0, bo + l*DDm, p_proj, TPR, DDm);
        k_ln<<<TPR/8, 256>>>(p_proj, g1 + l*DDm, bg1 + l*DDm);

        gemm_mma<true><<<dim3(FFD/128, TPR/128), 256, GSMEM>>>(
            p_h, BH(oWf1[l]), BL(oWf1[l], DDm, FFD), DDm,
            nullptr, nullptr, nullptr, 0, bf1 + l*FFD, p_ff, TPR, FFD);
        gemm_mma<false><<<dim3(DDm/128, TPR/128), 256, GSMEM>>>(
            p_ff, BH(oWf2[l]), BL(oWf2[l], FFD, DDm), FFD,
            nullptr, nullptr, nullptr, 0, bf2 + l*DDm, p_proj, TPR, DDm);
        k_ln<<<TPR/8, 256>>>(p_proj, g2 + l*DDm, bg2 + l*DDm);
    }

    k_out<<<TPR/8, 256>>>(Wout, out + (size_t)TPR * DDm);
}

// round 4
// speedup vs baseline: 2.1764x; 1.2946x over previous
#include <cuda_runtime.h>
#include <cuda_bf16.h>
#include <math.h>
#include <stdint.h>

#define NN   20000
#define EE   320000
#define TT   16
#define PP   4096
#define DIN  128
#define HH   256
#define DDm  512
#define FFD  2048
#define TPR  (TT*PP)   // 65536

// ---------------- scratch (static device globals; no allocation) ----------------
__device__ float g_deg[NN];
__device__ float g_agg[NN*HH];
__device__ float g_h1 [NN*HH];
__device__ float g_h2 [NN*HH];
__device__ float g_h   [(size_t)TPR*DDm];
__device__ float g_q   [(size_t)TPR*DDm];
__device__ float g_k   [(size_t)TPR*DDm];
__device__ float g_v   [(size_t)TPR*DDm];
__device__ float g_o   [(size_t)TPR*DDm];
__device__ float g_proj[(size_t)TPR*DDm];
__device__ float g_ff  [(size_t)TPR*FFD];
__device__ __nv_bfloat16 g_w[12976128];

// ---------------- helpers ----------------
__device__ __forceinline__ uint32_t smem_u32(const void* p) {
    uint32_t a;
    asm("{ .reg .u64 t; cvta.to.shared.u64 t, %1; cvt.u32.u64 %0, t; }" : "=r"(a) : "l"(p));
    return a;
}
__device__ __forceinline__ void ldsm4(uint32_t* r, uint32_t addr) {
    asm volatile("ldmatrix.sync.aligned.m8n8.x4.shared.b16 {%0,%1,%2,%3}, [%4];"
                 : "=r"(r[0]), "=r"(r[1]), "=r"(r[2]), "=r"(r[3]) : "r"(addr));
}
__device__ __forceinline__ void mma16816(float* c, const uint32_t* a, const uint32_t* b) {
    asm volatile("mma.sync.aligned.m16n8k16.row.col.f32.bf16.bf16.f32 "
                 "{%0,%1,%2,%3}, {%4,%5,%6,%7}, {%8,%9}, {%0,%1,%2,%3};"
                 : "+f"(c[0]), "+f"(c[1]), "+f"(c[2]), "+f"(c[3])
                 : "r"(a[0]), "r"(a[1]), "r"(a[2]), "r"(a[3]), "r"(b[0]), "r"(b[1]));
}
__device__ __forceinline__ uint32_t pack2(float a, float b) {
    __nv_bfloat162 t = __floats2bfloat162_rn(a, b);
    return *reinterpret_cast<uint32_t*>(&t);
}

// smem geometry: rows of 32 bf16 padded to 80 bytes (conflict-free ldmatrix)
#define RSTR  80
#define MATB  (128*RSTR)   // 10240 bytes per matrix tile
#define BUFB  (4*MATB)     // Ah, Al, Bh, Bl
#define GSMEM (2*BUFB)     // double buffered = 81920

// ---------------- HMMA GEMM: C = A1@W1 (+ rowscale(A2)@W2) + bias, opt ReLU ------
// A fp32 [M][K]; W pre-transposed bf16 hi/lo [N][K]. BM=BN=128, BK=32.
// bf16x3 compensation: Ah*Bh + Ah*Bl + Al*Bh, fp32 accum.
// rs2: if non-null, A2 rows are scaled by 1/max(rs2[row],1) (mean-agg division).
template<bool RELU>
__global__ void __launch_bounds__(256)
gemm_mma(const float* __restrict__ A1, const __nv_bfloat16* __restrict__ B1h,
         const __nv_bfloat16* __restrict__ B1l, int K1,
         const float* __restrict__ A2, const __nv_bfloat16* __restrict__ B2h,
         const __nv_bfloat16* __restrict__ B2l, int K2,
         const float* __restrict__ rs2,
         const float* __restrict__ bias, float* __restrict__ C, int M, int N) {
    extern __shared__ char smb[];
    const uint32_t sb = smem_u32(smb);
    const int tid = threadIdx.x, lane = tid & 31, wid = tid >> 5;
    const int bRow = blockIdx.y * 128, bCol = blockIdx.x * 128;
    const int wm = wid & 3, wn = wid >> 2;          // warp tile (wm*32, wn*64)
    const int lrow = tid >> 1, lhalf = tid & 1;     // staging: row 0..127, half 0..1

    const int nc1 = K1 >> 5;
    const int nc  = nc1 + (K2 >> 5);

    float acc[2][8][4];
#pragma unroll
    for (int i = 0; i < 2; i++)
#pragma unroll
        for (int j = 0; j < 8; j++)
#pragma unroll
            for (int q = 0; q < 4; q++) acc[i][j][q] = 0.f;

    float a_st[16];
    uint4 bh_st[2], bl_st[2];

#define GLOAD(cc) do {                                                          \
    const float* A_; const __nv_bfloat16 *Bh_, *Bl_; int K_, k0_; bool sc_;     \
    if ((cc) < nc1) { A_ = A1; Bh_ = B1h; Bl_ = B1l; K_ = K1; k0_ = (cc) << 5;  \
                      sc_ = false; }                                            \
    else { A_ = A2; Bh_ = B2h; Bl_ = B2l; K_ = K2; k0_ = ((cc) - nc1) << 5;     \
           sc_ = (rs2 != nullptr); }                                            \
    const int grow_ = bRow + lrow;                                              \
    if (grow_ < M) {                                                            \
        const float* ap_ = A_ + (size_t)grow_ * K_ + k0_ + lhalf * 16;          \
        *(float4*)(a_st + 0)  = ((const float4*)ap_)[0];                        \
        *(float4*)(a_st + 4)  = ((const float4*)ap_)[1];                        \
        *(float4*)(a_st + 8)  = ((const float4*)ap_)[2];                        \
        *(float4*)(a_st + 12) = ((const float4*)ap_)[3];                        \
        if (sc_) {                                                              \
            float iv_ = 1.0f / fmaxf(rs2[grow_], 1.0f);                         \
            _Pragma("unroll") for (int j_ = 0; j_ < 16; j_++) a_st[j_] *= iv_;  \
        }                                                                       \
    } else {                                                                    \
        _Pragma("unroll") for (int j_ = 0; j_ < 16; j_++) a_st[j_] = 0.f;       \
    }                                                                           \
    const size_t bo_ = (size_t)(bCol + lrow) * K_ + k0_ + lhalf * 16;           \
    bh_st[0] = ((const uint4*)(Bh_ + bo_))[0];                                  \
    bh_st[1] = ((const uint4*)(Bh_ + bo_))[1];                                  \
    bl_st[0] = ((const uint4*)(Bl_ + bo_))[0];                                  \
    bl_st[1] = ((const uint4*)(Bl_ + bo_))[1];                                  \
} while (0)

#define SSTORE(buf) do {                                                        \
    char* base_ = smb + (buf) * BUFB;                                          \
    const uint32_t ro_ = lrow * RSTR + lhalf * 32;                              \
    uint32_t hi_[8], lo_[8];                                                    \
    _Pragma("unroll") for (int j_ = 0; j_ < 8; j_++) {                          \
        float f0_ = a_st[2*j_], f1_ = a_st[2*j_+1];                             \
        __nv_bfloat16 h0_ = __float2bfloat16(f0_), h1_ = __float2bfloat16(f1_); \
        float v0_ = __bfloat162float(h0_), v1_ = __bfloat162float(h1_);         \
        hi_[j_] = pack2(v0_, v1_);                                              \
        lo_[j_] = pack2(f0_ - v0_, f1_ - v1_);                                  \
    }                                                                           \
    *(uint4*)(base_ + ro_)             = make_uint4(hi_[0],hi_[1],hi_[2],hi_[3]);\
    *(uint4*)(base_ + ro_ + 16)        = make_uint4(hi_[4],hi_[5],hi_[6],hi_[7]);\
    *(uint4*)(base_ + MATB + ro_)      = make_uint4(lo_[0],lo_[1],lo_[2],lo_[3]);\
    *(uint4*)(base_ + MATB + ro_ + 16) = make_uint4(lo_[4],lo_[5],lo_[6],lo_[7]);\
    *(uint4*)(base_ + 2*MATB + ro_)      = bh_st[0];                            \
    *(uint4*)(base_ + 2*MATB + ro_ + 16) = bh_st[1];                            \
    *(uint4*)(base_ + 3*MATB + ro_)      = bl_st[0];                            \
    *(uint4*)(base_ + 3*MATB + ro_ + 16) = bl_st[1];                            \
} while (0)

#define COMPUTE(buf) do {                                                       \
    const uint32_t ah_ = sb + (buf) * BUFB;                                     \
    const uint32_t al_ = ah_ + MATB, bhp_ = ah_ + 2*MATB, blp_ = ah_ + 3*MATB;  \
    _Pragma("unroll") for (int ks_ = 0; ks_ < 2; ks_++) {                       \
        uint32_t aH_[2][4], aL_[2][4], bH_[4][4], bL_[4][4];                    \
        const int arow_ = wm * 32 + (lane & 15);                                \
        const int acol_ = ks_ * 32 + ((lane >> 4) << 4);                        \
        ldsm4(aH_[0], ah_ + arow_ * RSTR + acol_);                              \
        ldsm4(aH_[1], ah_ + (arow_ + 16) * RSTR + acol_);                       \
        ldsm4(aL_[0], al_ + arow_ * RSTR + acol_);                              \
        ldsm4(aL_[1], al_ + (arow_ + 16) * RSTR + acol_);                       \
        const int br_ = lane & 7, bg_ = lane >> 3;                              \
        const int brow_ = wn * 64 + ((bg_ >> 1) << 3) + br_;                    \
        const int bcol_ = ks_ * 32 + ((bg_ & 1) << 4);                          \
        _Pragma("unroll") for (int nj_ = 0; nj_ < 4; nj_++) {                   \
            ldsm4(bH_[nj_], bhp_ + (brow_ + nj_ * 16) * RSTR + bcol_);          \
            ldsm4(bL_[nj_], blp_ + (brow_ + nj_ * 16) * RSTR + bcol_);          \
        }                                                                       \
        _Pragma("unroll") for (int mi_ = 0; mi_ < 2; mi_++)                     \
        _Pragma("unroll") for (int ni_ = 0; ni_ < 8; ni_++) {                   \
            const uint32_t* bh2_ = &bH_[ni_ >> 1][(ni_ & 1) * 2];               \
            const uint32_t* bl2_ = &bL_[ni_ >> 1][(ni_ & 1) * 2];               \
            mma16816(acc[mi_][ni_], aH_[mi_], bh2_);                            \
            mma16816(acc[mi_][ni_], aH_[mi_], bl2_);                            \
            mma16816(acc[mi_][ni_], aL_[mi_], bh2_);                            \
        }                                                                       \
    }                                                                           \
} while (0)

    GLOAD(0);
    SSTORE(0);
    __syncthreads();
    for (int c = 0; c < nc; c++) {
        if (c + 1 < nc) GLOAD(c + 1);
        COMPUTE(c & 1);
        if (c + 1 < nc) SSTORE((c + 1) & 1);
        __syncthreads();
    }

    // epilogue
#pragma unroll
    for (int mi = 0; mi < 2; mi++) {
        const int r0 = bRow + wm * 32 + mi * 16 + (lane >> 2);
#pragma unroll
        for (int ni = 0; ni < 8; ni++) {
            const int col = bCol + wn * 64 + ni * 8 + (lane & 3) * 2;
            const float b0 = bias[col], b1 = bias[col + 1];
            if (r0 < M) {
                float c0 = acc[mi][ni][0] + b0, c1 = acc[mi][ni][1] + b1;
                if (RELU) { c0 = fmaxf(c0, 0.f); c1 = fmaxf(c1, 0.f); }
                *(float2*)(C + (size_t)r0 * N + col) = make_float2(c0, c1);
            }
            if (r0 + 8 < M) {
                float c2 = acc[mi][ni][2] + b0, c3 = acc[mi][ni][3] + b1;
                if (RELU) { c2 = fmaxf(c2, 0.f); c3 = fmaxf(c3, 0.f); }
                *(float2*)(C + (size_t)(r0 + 8) * N + col) = make_float2(c2, c3);
            }
        }
    }
#undef GLOAD
#undef SSTORE
#undef COMPUTE
}

// ---------------- weight prep: W[K][N] fp32 -> Th/Tl [N][K] bf16 ----------------
__global__ void k_wprep(const float* __restrict__ W, __nv_bfloat16* __restrict__ Th,
                        __nv_bfloat16* __restrict__ Tl, int K, int N) {
    __shared__ float s[32][33];
    int n0 = blockIdx.x * 32, k0 = blockIdx.y * 32;
    for (int r = threadIdx.y; r < 32; r += 8)
        s[r][threadIdx.x] = W[(size_t)(k0 + r) * N + n0 + threadIdx.x];
    __syncthreads();
    for (int r = threadIdx.y; r < 32; r += 8) {
        float f = s[threadIdx.x][r];
        __nv_bfloat16 hb = __float2bfloat16(f);
        float hv = __bfloat162float(hb);
        size_t o = (size_t)(n0 + r) * K + k0 + threadIdx.x;
        Th[o] = hb;
        Tl[o] = __float2bfloat16(f - hv);
    }
}

// ---------------- utility kernels ----------------
__global__ void k_zero(float* __restrict__ p, int n4) {
    int i = blockIdx.x * blockDim.x + threadIdx.x;
    if (i < n4) ((float4*)p)[i] = make_float4(0.f, 0.f, 0.f, 0.f);
}
__global__ void k_deg(const int* __restrict__ dst) {
    int e = blockIdx.x * blockDim.x + threadIdx.x;
    if (e < EE) atomicAdd(&g_deg[dst[e]], 1.0f);
}
// scatter raw sums: agg[dst] += x[src], one v4 reduction per thread
__global__ void k_scatter(const float* __restrict__ x, const int* __restrict__ src,
                          const int* __restrict__ dst, int lg) {
    int i  = blockIdx.x * blockDim.x + threadIdx.x;
    int e  = i >> lg;
    if (e >= EE) return;
    int F4 = 1 << lg;
    int c4 = i & (F4 - 1);
    int s = src[e], d = dst[e];
    float4 xv = ((const float4*)x)[(size_t)s * F4 + c4];
    float* ap = g_agg + ((size_t)d * F4 + c4) * 4;
    asm volatile("red.global.add.v4.f32 [%0], {%1, %2, %3, %4};"
                 :: "l"(ap), "f"(xv.x), "f"(xv.y), "f"(xv.z), "f"(xv.w) : "memory");
}
__global__ void k_l2norm() {
    int w = threadIdx.x >> 5, lane = threadIdx.x & 31;
    int row = blockIdx.x * 8 + w;
    if (row >= NN) return;
    float* p = g_h2 + (size_t)row * HH;
    float v[8]; float ss = 0.f;
#pragma unroll
    for (int i = 0; i < 8; i++) { v[i] = p[lane + i * 32]; ss += v[i] * v[i]; }
#pragma unroll
    for (int o = 16; o; o >>= 1) ss += __shfl_xor_sync(0xffffffffu, ss, o);
    float inv = 1.0f / fmaxf(sqrtf(ss), 1e-12f);
#pragma unroll
    for (int i = 0; i < 8; i++) p[lane + i * 32] = v[i] * inv;
}
__global__ void k_gather(const int* __restrict__ idx, float* __restrict__ att_out,
                         int t, int off) {
    int i = blockIdx.x * blockDim.x + threadIdx.x;
    if (i >= PP * HH) return;
    int p = i >> 8, c = i & 255;
    int n = idx[p];
    float val = g_h2[(size_t)n * HH + c];
    size_t o = ((size_t)(t * PP + p)) * DDm + off + c;
    att_out[o] = val;
    g_h[o] = val;
}
__global__ void k_attn() {
    int p = blockIdx.x, h = blockIdx.y;
    int tid = threadIdx.x;
    __shared__ float qs[TT][64], ks[TT][64], vs[TT][64];
    __shared__ float att[TT][4];
    size_t base = (size_t)p * DDm + h * 64 + tid;
#pragma unroll
    for (int t = 0; t < TT; t++) {
        size_t off = (size_t)t * PP * DDm + base;
        qs[t][tid] = g_q[off];
        ks[t][tid] = g_k[off];
        vs[t][tid] = g_v[off];
    }
    __syncthreads();
    {
        int t = tid >> 2, j = tid & 3, s = t - j;
        float sc = -INFINITY;
        if (s >= 0) {
            float a = 0.f;
#pragma unroll
            for (int d = 0; d < 64; d++) a += qs[t][d] * ks[s][d];
            sc = a * 0.125f;
        }
        att[t][j] = sc;
    }
    __syncthreads();
    if (tid < TT) {
        float m = -INFINITY;
#pragma unroll
        for (int j = 0; j < 4; j++) m = fmaxf(m, att[tid][j]);
        float sum = 0.f, e[4];
#pragma unroll
        for (int j = 0; j < 4; j++) {
            float x = att[tid][j];
            float ee = (x == -INFINITY) ? 0.f : expf(x - m);
            e[j] = ee; sum += ee;
        }
        float inv = 1.0f / sum;
#pragma unroll
        for (int j = 0; j < 4; j++) att[tid][j] = e[j] * inv;
    }
    __syncthreads();
#pragma unroll
    for (int t = 0; t < TT; t++) {
        float a = 0.f;
#pragma unroll
        for (int j = 0; j < 4; j++) {
            int s = t - j;
            if (s >= 0) a += att[t][j] * vs[s][tid];
        }
        g_o[(size_t)t * PP * DDm + base] = a;
    }
}
__global__ void k_ln(const float* __restrict__ r, const float* __restrict__ g,
                     const float* __restrict__ b) {
    int w = threadIdx.x >> 5, lane = threadIdx.x & 31;
    size_t row = (size_t)blockIdx.x * 8 + w;
    float* xr = g_h + row * DDm;
    const float* rr = r + row * DDm;
    float v[16]; float s = 0.f;
#pragma unroll
    for (int i = 0; i < 16; i++) {
        int c = lane + i * 32;
        float t = xr[c] + rr[c];
        v[i] = t; s += t;
    }
#pragma unroll
    for (int o = 16; o; o >>= 1) s += __shfl_xor_sync(0xffffffffu, s, o);
    float mean = s * (1.0f / DDm);
    float vs = 0.f;
#pragma unroll
    for (int i = 0; i < 16; i++) { float d = v[i] - mean; vs += d * d; }
#pragma unroll
    for (int o = 16; o; o >>= 1) vs += __shfl_xor_sync(0xffffffffu, vs, o);
    float inv = rsqrtf(vs * (1.0f / DDm) + 1e-5f);
#pragma unroll
    for (int i = 0; i < 16; i++) {
        int c = lane + i * 32;
        xr[c] = (v[i] - mean) * inv * g[c] + b[c];
    }
}
__global__ void k_out(const float* __restrict__ wout, float* __restrict__ out) {
    int w = threadIdx.x >> 5, lane = threadIdx.x & 31;
    size_t row = (size_t)blockIdx.x * 8 + w;
    const float* hr = g_h + row * DDm;
    float s = 0.f;
#pragma unroll
    for (int i = 0; i < 16; i++) { int c = lane + i * 32; s += hr[c] * wout[c]; }
#pragma unroll
    for (int o = 16; o; o >>= 1) s += __shfl_xor_sync(0xffffffffu, s, o);
    if (lane == 0) out[row] = s;
}

// =======================================================================================
extern "C" void kernel_launch(void* const* d_in, const int* in_sizes, int n_in,
                              void* d_out, int out_size) {
    const float* x_i  = (const float*)d_in[0];
    const float* x_j  = (const float*)d_in[1];
    const int* src_i  = (const int*)d_in[2];
    const int* dst_i  = (const int*)d_in[3];
    const int* src_j  = (const int*)d_in[4];
    const int* dst_j  = (const int*)d_in[5];
    const int* idx_i  = (const int*)d_in[6];
    const int* idx_j  = (const int*)d_in[7];
    const float* W1s  = (const float*)d_in[8];
    const float* W1n  = (const float*)d_in[9];
    const float* b1   = (const float*)d_in[10];
    const float* W2s  = (const float*)d_in[11];
    const float* W2n  = (const float*)d_in[12];
    const float* b2   = (const float*)d_in[13];
    const float* Wq   = (const float*)d_in[14];
    const float* Wk   = (const float*)d_in[15];
    const float* Wv   = (const float*)d_in[16];
    const float* bq   = (const float*)d_in[17];
    const float* bk   = (const float*)d_in[18];
    const float* bv   = (const float*)d_in[19];
    const float* Wo   = (const float*)d_in[20];
    const float* bo   = (const float*)d_in[21];
    const float* Wf1  = (const float*)d_in[22];
    const float* bf1  = (const float*)d_in[23];
    const float* Wf2  = (const float*)d_in[24];
    const float* bf2  = (const float*)d_in[25];
    const float* g1   = (const float*)d_in[26];
    const float* bg1  = (const float*)d_in[27];
    const float* g2   = (const float*)d_in[28];
    const float* bg2  = (const float*)d_in[29];
    const float* Wout = (const float*)d_in[30];
    float* out = (float*)d_out;

    float *p_agg, *p_h1, *p_h2, *p_deg, *p_h, *p_q, *p_k, *p_v, *p_o, *p_proj, *p_ff;
    __nv_bfloat16* p_w;
    cudaGetSymbolAddress((void**)&p_deg,  g_deg);
    cudaGetSymbolAddress((void**)&p_agg,  g_agg);
    cudaGetSymbolAddress((void**)&p_h1,   g_h1);
    cudaGetSymbolAddress((void**)&p_h2,   g_h2);
    cudaGetSymbolAddress((void**)&p_h,    g_h);
    cudaGetSymbolAddress((void**)&p_q,    g_q);
    cudaGetSymbolAddress((void**)&p_k,    g_k);
    cudaGetSymbolAddress((void**)&p_v,    g_v);
    cudaGetSymbolAddress((void**)&p_o,    g_o);
    cudaGetSymbolAddress((void**)&p_proj, g_proj);
    cudaGetSymbolAddress((void**)&p_ff,   g_ff);
    cudaGetSymbolAddress((void**)&p_w,    g_w);

    cudaFuncSetAttribute(gemm_mma<false>, cudaFuncAttributeMaxDynamicSharedMemorySize, GSMEM);
    cudaFuncSetAttribute(gemm_mma<true>,  cudaFuncAttributeMaxDynamicSharedMemorySize, GSMEM);

    size_t off = 0;
    auto prep = [&](const float* W, int K, int N) -> size_t {
        size_t b = off;
        k_wprep<<<dim3(N/32, K/32), dim3(32, 8)>>>(W, p_w + b, p_w + b + (size_t)K*N, K, N);
        off += 2 * (size_t)K * N;
        return b;
    };
    size_t oW1s = prep(W1s, DIN, HH), oW1n = prep(W1n, DIN, HH);
    size_t oW2s = prep(W2s, HH, HH),  oW2n = prep(W2n, HH, HH);
    size_t oWq[2], oWk[2], oWv[2], oWo[2], oWf1[2], oWf2[2];
    for (int l = 0; l < 2; l++) {
        oWq[l]  = prep(Wq  + (size_t)l*DDm*DDm, DDm, DDm);
        oWk[l]  = prep(Wk  + (size_t)l*DDm*DDm, DDm, DDm);
        oWv[l]  = prep(Wv  + (size_t)l*DDm*DDm, DDm, DDm);
        oWo[l]  = prep(Wo  + (size_t)l*DDm*DDm, DDm, DDm);
        oWf1[l] = prep(Wf1 + (size_t)l*DDm*FFD, DDm, FFD);
        oWf2[l] = prep(Wf2 + (size_t)l*FFD*DDm, FFD, DDm);
    }
    auto BH = [&](size_t b) { return p_w + b; };
    auto BL = [&](size_t b, size_t K, size_t N) { return p_w + b + K * N; };

    for (int t = 0; t < TT; t++) {
        for (int gsel = 0; gsel < 2; gsel++) {
            const float* x  = (gsel ? x_j  : x_i ) + (size_t)t * NN * DIN;
            const int* src  = (gsel ? src_j: src_i) + (size_t)t * EE;
            const int* dstp = (gsel ? dst_j: dst_i) + (size_t)t * EE;
            const int* idx  = (gsel ? idx_j: idx_i) + (size_t)t * PP;

            k_zero<<<(NN/4 + 255)/256, 256>>>(p_deg, NN/4);
            k_deg <<<(EE + 255)/256, 256>>>(dstp);

            k_zero   <<<(NN*DIN/4 + 255)/256, 256>>>(p_agg, NN*DIN/4);
            k_scatter<<<(EE*(DIN/4) + 255)/256, 256>>>(x, src, dstp, 5);
            gemm_mma<true><<<dim3(HH/128, (NN + 127)/128), 256, GSMEM>>>(
                x, BH(oW1s), BL(oW1s, DIN, HH), DIN,
                p_agg, BH(oW1n), BL(oW1n, DIN, HH), DIN, p_deg, b1, p_h1, NN, HH);

            k_zero   <<<(NN*HH/4 + 255)/256, 256>>>(p_agg, NN*HH/4);
            k_scatter<<<(EE*(HH/4) + 255)/256, 256>>>(p_h1, src, dstp, 6);
            gemm_mma<false><<<dim3(HH/128, (NN + 127)/128), 256, GSMEM>>>(
                p_h1, BH(oW2s), BL(oW2s, HH, HH), HH,
                p_agg, BH(oW2n), BL(oW2n, HH, HH), HH, p_deg, b2, p_h2, NN, HH);

            k_l2norm<<<(NN + 7)/8, 256>>>();
            k_gather<<<(PP*HH + 255)/256, 256>>>(idx, out, t, gsel * HH);
        }
    }

    for (int l = 0; l < 2; l++) {
        gemm_mma<false><<<dim3(DDm/128, TPR/128), 256, GSMEM>>>(
            p_h, BH(oWq[l]), BL(oWq[l], DDm, DDm), DDm,
            nullptr, nullptr, nullptr, 0, nullptr, bq + l*DDm, p_q, TPR, DDm);
        gemm_mma<false><<<dim3(DDm/128, TPR/128), 256, GSMEM>>>(
            p_h, BH(oWk[l]), BL(oWk[l], DDm, DDm), DDm,
            nullptr, nullptr, nullptr, 0, nullptr, bk + l*DDm, p_k, TPR, DDm);
        gemm_mma<false><<<dim3(DDm/128, TPR/128), 256, GSMEM>>>(
            p_h, BH(oWv[l]), BL(oWv[l], DDm, DDm), DDm,
            nullptr, nullptr, nullptr, 0, nullptr, bv + l*DDm, p_v, TPR, DDm);

        k_attn<<<dim3(PP, 8), 64>>>();

        gemm_mma<false><<<dim3(DDm/128, TPR/128), 256, GSMEM>>>(
            p_o, BH(oWo[l]), BL(oWo[l], DDm, DDm), DDm,
            nullptr, nullptr, nullptr, 0, nullptr, bo + l*DDm, p_proj, TPR, DDm);
        k_ln<<<TPR/8, 256>>>(p_proj, g1 + l*DDm, bg1 + l*DDm);

        gemm_mma<true><<<dim3(FFD/128, TPR/128), 256, GSMEM>>>(
            p_h, BH(oWf1[l]), BL(oWf1[l], DDm, FFD), DDm,
            nullptr, nullptr, nullptr, 0, nullptr, bf1 + l*FFD, p_ff, TPR, FFD);
        gemm_mma<false><<<dim3(DDm/128, TPR/128), 256, GSMEM>>>(
            p_ff, BH(oWf2[l]), BL(oWf2[l], FFD, DDm), FFD,
            nullptr, nullptr, nullptr, 0, nullptr, bf2 + l*DDm, p_proj, TPR, DDm);
        k_ln<<<TPR/8, 256>>>(p_proj, g2 + l*DDm, bg2 + l*DDm);
    }

    k_out<<<TPR/8, 256>>>(Wout, out + (size_t)TPR * DDm);
}

// round 5
// speedup vs baseline: 2.3584x; 1.0836x over previous
#include <cuda_runtime.h>
#include <cuda_bf16.h>
#include <math.h>
#include <stdint.h>

#define NN   20000
#define EE   320000
#define TT   16
#define PP   4096
#define DIN  128
#define HH   256
#define DDm  512
#define FFD  2048
#define TPR  (TT*PP)   // 65536
#define MB   (TT*NN)   // 320000 batched rows

// ---------------- scratch (static device globals; no allocation) ----------------
__device__ float g_degB[MB];
__device__ float g_aggB[(size_t)MB*HH];
__device__ float g_h1B [(size_t)MB*HH];
__device__ float g_h2B [(size_t)MB*HH];
__device__ float g_h   [(size_t)TPR*DDm];
__device__ float g_q   [(size_t)TPR*DDm];
__device__ float g_k   [(size_t)TPR*DDm];
__device__ float g_v   [(size_t)TPR*DDm];
__device__ float g_o   [(size_t)TPR*DDm];
__device__ float g_proj[(size_t)TPR*DDm];
__device__ float g_ff  [(size_t)TPR*FFD];
__device__ __nv_bfloat16 g_w[12976128];

// ---------------- helpers ----------------
__device__ __forceinline__ uint32_t smem_u32(const void* p) {
    uint32_t a;
    asm("{ .reg .u64 t; cvta.to.shared.u64 t, %1; cvt.u32.u64 %0, t; }" : "=r"(a) : "l"(p));
    return a;
}
__device__ __forceinline__ void ldsm4(uint32_t* r, uint32_t addr) {
    asm volatile("ldmatrix.sync.aligned.m8n8.x4.shared.b16 {%0,%1,%2,%3}, [%4];"
                 : "=r"(r[0]), "=r"(r[1]), "=r"(r[2]), "=r"(r[3]) : "r"(addr));
}
__device__ __forceinline__ void mma16816(float* c, const uint32_t* a, const uint32_t* b) {
    asm volatile("mma.sync.aligned.m16n8k16.row.col.f32.bf16.bf16.f32 "
                 "{%0,%1,%2,%3}, {%4,%5,%6,%7}, {%8,%9}, {%0,%1,%2,%3};"
                 : "+f"(c[0]), "+f"(c[1]), "+f"(c[2]), "+f"(c[3])
                 : "r"(a[0]), "r"(a[1]), "r"(a[2]), "r"(a[3]), "r"(b[0]), "r"(b[1]));
}
__device__ __forceinline__ uint32_t pack2(float a, float b) {
    __nv_bfloat162 t = __floats2bfloat162_rn(a, b);
    return *reinterpret_cast<uint32_t*>(&t);
}

// smem geometry: rows of 32 bf16 padded to 80 bytes (conflict-free ldmatrix)
#define RSTR  80
#define MATB  (128*RSTR)   // 10240 bytes per matrix tile
#define BUFB  (4*MATB)     // Ah, Al, Bh, Bl
#define GSMEM (2*BUFB)     // double buffered = 81920

// ---------------- HMMA GEMM: C = A1@W1 (+ rowscale(A2)@W2) + bias, opt ReLU ------
// A fp32 [M][K]; W pre-transposed bf16 hi/lo [N][K]. BM=BN=128, BK=32.
// bf16x3 compensation: Ah*Bh + Ah*Bl + Al*Bh, fp32 accum.
// rs2: if non-null, A2 rows are scaled by 1/max(rs2[row],1) (mean-agg division).
template<bool RELU>
__global__ void __launch_bounds__(256)
gemm_mma(const float* __restrict__ A1, const __nv_bfloat16* __restrict__ B1h,
         const __nv_bfloat16* __restrict__ B1l, int K1,
         const float* __restrict__ A2, const __nv_bfloat16* __restrict__ B2h,
         const __nv_bfloat16* __restrict__ B2l, int K2,
         const float* __restrict__ rs2,
         const float* __restrict__ bias, float* __restrict__ C, int M, int N) {
    extern __shared__ char smb[];
    const uint32_t sb = smem_u32(smb);
    const int tid = threadIdx.x, lane = tid & 31, wid = tid >> 5;
    const int bRow = blockIdx.y * 128, bCol = blockIdx.x * 128;
    const int wm = wid & 3, wn = wid >> 2;          // warp tile (wm*32, wn*64)
    const int lrow = tid >> 1, lhalf = tid & 1;     // staging: row 0..127, half 0..1

    const int nc1 = K1 >> 5;
    const int nc  = nc1 + (K2 >> 5);

    float acc[2][8][4];
#pragma unroll
    for (int i = 0; i < 2; i++)
#pragma unroll
        for (int j = 0; j < 8; j++)
#pragma unroll
            for (int q = 0; q < 4; q++) acc[i][j][q] = 0.f;

    float a_st[16];
    uint4 bh_st[2], bl_st[2];

#define GLOAD(cc) do {                                                          \
    const float* A_; const __nv_bfloat16 *Bh_, *Bl_; int K_, k0_; bool sc_;     \
    if ((cc) < nc1) { A_ = A1; Bh_ = B1h; Bl_ = B1l; K_ = K1; k0_ = (cc) << 5;  \
                      sc_ = false; }                                            \
    else { A_ = A2; Bh_ = B2h; Bl_ = B2l; K_ = K2; k0_ = ((cc) - nc1) << 5;     \
           sc_ = (rs2 != nullptr); }                                            \
    const int grow_ = bRow + lrow;                                              \
    if (grow_ < M) {                                                            \
        const float* ap_ = A_ + (size_t)grow_ * K_ + k0_ + lhalf * 16;          \
        *(float4*)(a_st + 0)  = ((const float4*)ap_)[0];                        \
        *(float4*)(a_st + 4)  = ((const float4*)ap_)[1];                        \
        *(float4*)(a_st + 8)  = ((const float4*)ap_)[2];                        \
        *(float4*)(a_st + 12) = ((const float4*)ap_)[3];                        \
        if (sc_) {                                                              \
            float iv_ = 1.0f / fmaxf(rs2[grow_], 1.0f);                         \
            _Pragma("unroll") for (int j_ = 0; j_ < 16; j_++) a_st[j_] *= iv_;  \
        }                                                                       \
    } else {                                                                    \
        _Pragma("unroll") for (int j_ = 0; j_ < 16; j_++) a_st[j_] = 0.f;       \
    }                                                                           \
    const size_t bo_ = (size_t)(bCol + lrow) * K_ + k0_ + lhalf * 16;           \
    bh_st[0] = ((const uint4*)(Bh_ + bo_))[0];                                  \
    bh_st[1] = ((const uint4*)(Bh_ + bo_))[1];                                  \
    bl_st[0] = ((const uint4*)(Bl_ + bo_))[0];                                  \
    bl_st[1] = ((const uint4*)(Bl_ + bo_))[1];                                  \
} while (0)

#define SSTORE(buf) do {                                                        \
    char* base_ = smb + (buf) * BUFB;                                          \
    const uint32_t ro_ = lrow * RSTR + lhalf * 32;                              \
    uint32_t hi_[8], lo_[8];                                                    \
    _Pragma("unroll") for (int j_ = 0; j_ < 8; j_++) {                          \
        float f0_ = a_st[2*j_], f1_ = a_st[2*j_+1];                             \
        __nv_bfloat16 h0_ = __float2bfloat16(f0_), h1_ = __float2bfloat16(f1_); \
        float v0_ = __bfloat162float(h0_), v1_ = __bfloat162float(h1_);         \
        hi_[j_] = pack2(v0_, v1_);                                              \
        lo_[j_] = pack2(f0_ - v0_, f1_ - v1_);                                  \
    }                                                                           \
    *(uint4*)(base_ + ro_)             = make_uint4(hi_[0],hi_[1],hi_[2],hi_[3]);\
    *(uint4*)(base_ + ro_ + 16)        = make_uint4(hi_[4],hi_[5],hi_[6],hi_[7]);\
    *(uint4*)(base_ + MATB + ro_)      = make_uint4(lo_[0],lo_[1],lo_[2],lo_[3]);\
    *(uint4*)(base_ + MATB + ro_ + 16) = make_uint4(lo_[4],lo_[5],lo_[6],lo_[7]);\
    *(uint4*)(base_ + 2*MATB + ro_)      = bh_st[0];                            \
    *(uint4*)(base_ + 2*MATB + ro_ + 16) = bh_st[1];                            \
    *(uint4*)(base_ + 3*MATB + ro_)      = bl_st[0];                            \
    *(uint4*)(base_ + 3*MATB + ro_ + 16) = bl_st[1];                            \
} while (0)

#define COMPUTE(buf) do {                                                       \
    const uint32_t ah_ = sb + (buf) * BUFB;                                     \
    const uint32_t al_ = ah_ + MATB, bhp_ = ah_ + 2*MATB, blp_ = ah_ + 3*MATB;  \
    _Pragma("unroll") for (int ks_ = 0; ks_ < 2; ks_++) {                       \
        uint32_t aH_[2][4], aL_[2][4], bH_[4][4], bL_[4][4];                    \
        const int arow_ = wm * 32 + (lane & 15);                                \
        const int acol_ = ks_ * 32 + ((lane >> 4) << 4);                        \
        ldsm4(aH_[0], ah_ + arow_ * RSTR + acol_);                              \
        ldsm4(aH_[1], ah_ + (arow_ + 16) * RSTR + acol_);                       \
        ldsm4(aL_[0], al_ + arow_ * RSTR + acol_);                              \
        ldsm4(aL_[1], al_ + (arow_ + 16) * RSTR + acol_);                       \
        const int br_ = lane & 7, bg_ = lane >> 3;                              \
        const int brow_ = wn * 64 + ((bg_ >> 1) << 3) + br_;                    \
        const int bcol_ = ks_ * 32 + ((bg_ & 1) << 4);                          \
        _Pragma("unroll") for (int nj_ = 0; nj_ < 4; nj_++) {                   \
            ldsm4(bH_[nj_], bhp_ + (brow_ + nj_ * 16) * RSTR + bcol_);          \
            ldsm4(bL_[nj_], blp_ + (brow_ + nj_ * 16) * RSTR + bcol_);          \
        }                                                                       \
        _Pragma("unroll") for (int mi_ = 0; mi_ < 2; mi_++)                     \
        _Pragma("unroll") for (int ni_ = 0; ni_ < 8; ni_++) {                   \
            const uint32_t* bh2_ = &bH_[ni_ >> 1][(ni_ & 1) * 2];               \
            const uint32_t* bl2_ = &bL_[ni_ >> 1][(ni_ & 1) * 2];               \
            mma16816(acc[mi_][ni_], aH_[mi_], bh2_);                            \
            mma16816(acc[mi_][ni_], aH_[mi_], bl2_);                            \
            mma16816(acc[mi_][ni_], aL_[mi_], bh2_);                            \
        }                                                                       \
    }                                                                           \
} while (0)

    GLOAD(0);
    SSTORE(0);
    __syncthreads();
    for (int c = 0; c < nc; c++) {
        if (c + 1 < nc) GLOAD(c + 1);
        COMPUTE(c & 1);
        if (c + 1 < nc) SSTORE((c + 1) & 1);
        __syncthreads();
    }

    // epilogue
#pragma unroll
    for (int mi = 0; mi < 2; mi++) {
        const int r0 = bRow + wm * 32 + mi * 16 + (lane >> 2);
#pragma unroll
        for (int ni = 0; ni < 8; ni++) {
            const int col = bCol + wn * 64 + ni * 8 + (lane & 3) * 2;
            const float b0 = bias[col], b1 = bias[col + 1];
            if (r0 < M) {
                float c0 = acc[mi][ni][0] + b0, c1 = acc[mi][ni][1] + b1;
                if (RELU) { c0 = fmaxf(c0, 0.f); c1 = fmaxf(c1, 0.f); }
                *(float2*)(C + (size_t)r0 * N + col) = make_float2(c0, c1);
            }
            if (r0 + 8 < M) {
                float c2 = acc[mi][ni][2] + b0, c3 = acc[mi][ni][3] + b1;
                if (RELU) { c2 = fmaxf(c2, 0.f); c3 = fmaxf(c3, 0.f); }
                *(float2*)(C + (size_t)(r0 + 8) * N + col) = make_float2(c2, c3);
            }
        }
    }
#undef GLOAD
#undef SSTORE
#undef COMPUTE
}

// ---------------- weight prep: W[K][N] fp32 -> Th/Tl [N][K] bf16 ----------------
__global__ void k_wprep(const float* __restrict__ W, __nv_bfloat16* __restrict__ Th,
                        __nv_bfloat16* __restrict__ Tl, int K, int N) {
    __shared__ float s[32][33];
    int n0 = blockIdx.x * 32, k0 = blockIdx.y * 32;
    for (int r = threadIdx.y; r < 32; r += 8)
        s[r][threadIdx.x] = W[(size_t)(k0 + r) * N + n0 + threadIdx.x];
    __syncthreads();
    for (int r = threadIdx.y; r < 32; r += 8) {
        float f = s[threadIdx.x][r];
        __nv_bfloat16 hb = __float2bfloat16(f);
        float hv = __bfloat162float(hb);
        size_t o = (size_t)(n0 + r) * K + k0 + threadIdx.x;
        Th[o] = hb;
        Tl[o] = __float2bfloat16(f - hv);
    }
}

// ---------------- utility kernels ----------------
__global__ void k_zero(float* __restrict__ p, unsigned n4) {
    unsigned i = blockIdx.x * blockDim.x + threadIdx.x;
    if (i < n4) ((float4*)p)[i] = make_float4(0.f, 0.f, 0.f, 0.f);
}
// batched degree over all T timesteps: deg[t*NN + dst]
__global__ void k_degB(const int* __restrict__ dst, float* __restrict__ deg) {
    unsigned e = blockIdx.x * blockDim.x + threadIdx.x;
    if (e >= TT * EE) return;
    int t = e / EE;
    float* p = deg + (size_t)t * NN + dst[e];
    asm volatile("red.global.add.f32 [%0], %1;" :: "l"(p), "f"(1.0f) : "memory");
}
// batched scatter raw sums: agg[t*NN+dst] += x[t*NN+src], one v4 reduction/thread
__global__ void k_scatterB(const float* __restrict__ x, const int* __restrict__ src,
                           const int* __restrict__ dst, float* __restrict__ agg, int lg) {
    unsigned i = blockIdx.x * blockDim.x + threadIdx.x;
    unsigned e = i >> lg;
    if (e >= TT * EE) return;
    int F4 = 1 << lg;
    int c4 = i & (F4 - 1);
    int t = e / EE;
    size_t s = (size_t)t * NN + src[e], d = (size_t)t * NN + dst[e];
    float4 xv = ((const float4*)x)[s * F4 + c4];
    float* ap = agg + (d * F4 + c4) * 4;
    asm volatile("red.global.add.v4.f32 [%0], {%1, %2, %3, %4};"
                 :: "l"(ap), "f"(xv.x), "f"(xv.y), "f"(xv.z), "f"(xv.w) : "memory");
}
// fused L2-normalize + gather: warp per (t,p) row; reads h2B[t*NN+idx[t][p]]
__global__ void k_normgather(const float* __restrict__ h2, const int* __restrict__ idx,
                             float* __restrict__ att_out, float* __restrict__ hbuf, int off) {
    int w = threadIdx.x >> 5, lane = threadIdx.x & 31;
    unsigned tp = blockIdx.x * 8 + w;           // 0..TPR-1
    int t = tp >> 12, p = tp & 4095;
    int n = idx[t * PP + p];
    const float* row = h2 + ((size_t)t * NN + n) * HH;
    float v[8]; float ss = 0.f;
#pragma unroll
    for (int i = 0; i < 8; i++) { v[i] = row[lane + i * 32]; ss += v[i] * v[i]; }
#pragma unroll
    for (int o = 16; o; o >>= 1) ss += __shfl_xor_sync(0xffffffffu, ss, o);
    float inv = 1.0f / fmaxf(sqrtf(ss), 1e-12f);
    size_t o0 = (size_t)tp * DDm + off;
#pragma unroll
    for (int i = 0; i < 8; i++) {
        float val = v[i] * inv;
        att_out[o0 + lane + i * 32] = val;
        hbuf[o0 + lane + i * 32] = val;
    }
}
__global__ void k_attn() {
    int p = blockIdx.x, h = blockIdx.y;
    int tid = threadIdx.x;
    __shared__ float qs[TT][64], ks[TT][64], vs[TT][64];
    __shared__ float att[TT][4];
    size_t base = (size_t)p * DDm + h * 64 + tid;
#pragma unroll
    for (int t = 0; t < TT; t++) {
        size_t off = (size_t)t * PP * DDm + base;
        qs[t][tid] = g_q[off];
        ks[t][tid] = g_k[off];
        vs[t][tid] = g_v[off];
    }
    __syncthreads();
    {
        int t = tid >> 2, j = tid & 3, s = t - j;
        float sc = -INFINITY;
        if (s >= 0) {
            float a = 0.f;
#pragma unroll
            for (int d = 0; d < 64; d++) a += qs[t][d] * ks[s][d];
            sc = a * 0.125f;
        }
        att[t][j] = sc;
    }
    __syncthreads();
    if (tid < TT) {
        float m = -INFINITY;
#pragma unroll
        for (int j = 0; j < 4; j++) m = fmaxf(m, att[tid][j]);
        float sum = 0.f, e[4];
#pragma unroll
        for (int j = 0; j < 4; j++) {
            float x = att[tid][j];
            float ee = (x == -INFINITY) ? 0.f : expf(x - m);
            e[j] = ee; sum += ee;
        }
        float inv = 1.0f / sum;
#pragma unroll
        for (int j = 0; j < 4; j++) att[tid][j] = e[j] * inv;
    }
    __syncthreads();
#pragma unroll
    for (int t = 0; t < TT; t++) {
        float a = 0.f;
#pragma unroll
        for (int j = 0; j < 4; j++) {
            int s = t - j;
            if (s >= 0) a += att[t][j] * vs[s][tid];
        }
        g_o[(size_t)t * PP * DDm + base] = a;
    }
}
__global__ void k_ln(const float* __restrict__ r, const float* __restrict__ g,
                     const float* __restrict__ b) {
    int w = threadIdx.x >> 5, lane = threadIdx.x & 31;
    size_t row = (size_t)blockIdx.x * 8 + w;
    float* xr = g_h + row * DDm;
    const float* rr = r + row * DDm;
    float v[16]; float s = 0.f;
#pragma unroll
    for (int i = 0; i < 16; i++) {
        int c = lane + i * 32;
        float t = xr[c] + rr[c];
        v[i] = t; s += t;
    }
#pragma unroll
    for (int o = 16; o; o >>= 1) s += __shfl_xor_sync(0xffffffffu, s, o);
    float mean = s * (1.0f / DDm);
    float vs = 0.f;
#pragma unroll
    for (int i = 0; i < 16; i++) { float d = v[i] - mean; vs += d * d; }
#pragma unroll
    for (int o = 16; o; o >>= 1) vs += __shfl_xor_sync(0xffffffffu, vs, o);
    float inv = rsqrtf(vs * (1.0f / DDm) + 1e-5f);
#pragma unroll
    for (int i = 0; i < 16; i++) {
        int c = lane + i * 32;
        xr[c] = (v[i] - mean) * inv * g[c] + b[c];
    }
}
__global__ void k_out(const float* __restrict__ wout, float* __restrict__ out) {
    int w = threadIdx.x >> 5, lane = threadIdx.x & 31;
    size_t row = (size_t)blockIdx.x * 8 + w;
    const float* hr = g_h + row * DDm;
    float s = 0.f;
#pragma unroll
    for (int i = 0; i < 16; i++) { int c = lane + i * 32; s += hr[c] * wout[c]; }
#pragma unroll
    for (int o = 16; o; o >>= 1) s += __shfl_xor_sync(0xffffffffu, s, o);
    if (lane == 0) out[row] = s;
}

// =======================================================================================
extern "C" void kernel_launch(void* const* d_in, const int* in_sizes, int n_in,
                              void* d_out, int out_size) {
    const float* x_i  = (const float*)d_in[0];
    const float* x_j  = (const float*)d_in[1];
    const int* src_i  = (const int*)d_in[2];
    const int* dst_i  = (const int*)d_in[3];
    const int* src_j  = (const int*)d_in[4];
    const int* dst_j  = (const int*)d_in[5];
    const int* idx_i  = (const int*)d_in[6];
    const int* idx_j  = (const int*)d_in[7];
    const float* W1s  = (const float*)d_in[8];
    const float* W1n  = (const float*)d_in[9];
    const float* b1   = (const float*)d_in[10];
    const float* W2s  = (const float*)d_in[11];
    const float* W2n  = (const float*)d_in[12];
    const float* b2   = (const float*)d_in[13];
    const float* Wq   = (const float*)d_in[14];
    const float* Wk   = (const float*)d_in[15];
    const float* Wv   = (const float*)d_in[16];
    const float* bq   = (const float*)d_in[17];
    const float* bk   = (const float*)d_in[18];
    const float* bv   = (const float*)d_in[19];
    const float* Wo   = (const float*)d_in[20];
    const float* bo   = (const float*)d_in[21];
    const float* Wf1  = (const float*)d_in[22];
    const float* bf1  = (const float*)d_in[23];
    const float* Wf2  = (const float*)d_in[24];
    const float* bf2  = (const float*)d_in[25];
    const float* g1   = (const float*)d_in[26];
    const float* bg1  = (const float*)d_in[27];
    const float* g2   = (const float*)d_in[28];
    const float* bg2  = (const float*)d_in[29];
    const float* Wout = (const float*)d_in[30];
    float* out = (float*)d_out;

    float *p_degB, *p_aggB, *p_h1B, *p_h2B, *p_h, *p_q, *p_k, *p_v, *p_o, *p_proj, *p_ff;
    __nv_bfloat16* p_w;
    cudaGetSymbolAddress((void**)&p_degB, g_degB);
    cudaGetSymbolAddress((void**)&p_aggB, g_aggB);
    cudaGetSymbolAddress((void**)&p_h1B,  g_h1B);
    cudaGetSymbolAddress((void**)&p_h2B,  g_h2B);
    cudaGetSymbolAddress((void**)&p_h,    g_h);
    cudaGetSymbolAddress((void**)&p_q,    g_q);
    cudaGetSymbolAddress((void**)&p_k,    g_k);
    cudaGetSymbolAddress((void**)&p_v,    g_v);
    cudaGetSymbolAddress((void**)&p_o,    g_o);
    cudaGetSymbolAddress((void**)&p_proj, g_proj);
    cudaGetSymbolAddress((void**)&p_ff,   g_ff);
    cudaGetSymbolAddress((void**)&p_w,    g_w);

    cudaFuncSetAttribute(gemm_mma<false>, cudaFuncAttributeMaxDynamicSharedMemorySize, GSMEM);
    cudaFuncSetAttribute(gemm_mma<true>,  cudaFuncAttributeMaxDynamicSharedMemorySize, GSMEM);

    size_t off = 0;
    auto prep = [&](const float* W, int K, int N) -> size_t {
        size_t b = off;
        k_wprep<<<dim3(N/32, K/32), dim3(32, 8)>>>(W, p_w + b, p_w + b + (size_t)K*N, K, N);
        off += 2 * (size_t)K * N;
        return b;
    };
    size_t oW1s = prep(W1s, DIN, HH), oW1n = prep(W1n, DIN, HH);
    size_t oW2s = prep(W2s, HH, HH),  oW2n = prep(W2n, HH, HH);
    size_t oWq[2], oWk[2], oWv[2], oWo[2], oWf1[2], oWf2[2];
    for (int l = 0; l < 2; l++) {
        oWq[l]  = prep(Wq  + (size_t)l*DDm*DDm, DDm, DDm);
        oWk[l]  = prep(Wk  + (size_t)l*DDm*DDm, DDm, DDm);
        oWv[l]  = prep(Wv  + (size_t)l*DDm*DDm, DDm, DDm);
        oWo[l]  = prep(Wo  + (size_t)l*DDm*DDm, DDm, DDm);
        oWf1[l] = prep(Wf1 + (size_t)l*DDm*FFD, DDm, FFD);
        oWf2[l] = prep(Wf2 + (size_t)l*FFD*DDm, FFD, DDm);
    }
    auto BH = [&](size_t b) { return p_w + b; };
    auto BL = [&](size_t b, size_t K, size_t N) { return p_w + b + K * N; };

    // ---------- GraphSAGE: batched over all TT timesteps, per graph ----------
    for (int gsel = 0; gsel < 2; gsel++) {
        const float* x  = gsel ? x_j   : x_i;
        const int* src  = gsel ? src_j : src_i;
        const int* dstp = gsel ? dst_j : dst_i;
        const int* idx  = gsel ? idx_j : idx_i;

        // degree (batched)
        k_zero<<<(MB/4 + 255)/256, 256>>>(p_degB, MB/4);
        k_degB<<<(TT*EE + 255)/256, 256>>>(dstp, p_degB);

        // layer 1: scatter x (F=128), dual GEMM -> h1B
        k_zero   <<<((unsigned)(MB*(DIN/4)) + 255)/256, 256>>>(p_aggB, (unsigned)(MB*(DIN/4)));
        k_scatterB<<<((unsigned)(TT*EE*(DIN/4)) + 255)/256, 256>>>(x, src, dstp, p_aggB, 5);
        gemm_mma<true><<<dim3(HH/128, (MB + 127)/128), 256, GSMEM>>>(
            x, BH(oW1s), BL(oW1s, DIN, HH), DIN,
            p_aggB, BH(oW1n), BL(oW1n, DIN, HH), DIN, p_degB, b1, p_h1B, MB, HH);

        // layer 2: scatter h1 (F=256), dual GEMM -> h2B
        k_zero   <<<((unsigned)(MB*(HH/4)) + 255)/256, 256>>>(p_aggB, (unsigned)(MB*(HH/4)));
        k_scatterB<<<((unsigned)(TT*EE*(HH/4)) + 255)/256, 256>>>(p_h1B, src, dstp, p_aggB, 6);
        gemm_mma<false><<<dim3(HH/128, (MB + 127)/128), 256, GSMEM>>>(
            p_h1B, BH(oW2s), BL(oW2s, HH, HH), HH,
            p_aggB, BH(oW2n), BL(oW2n, HH, HH), HH, p_degB, b2, p_h2B, MB, HH);

        // fused l2-normalize + gather into att_in (out) and residual stream g_h
        k_normgather<<<TPR/8, 256>>>(p_h2B, idx, out, p_h, gsel * HH);
    }

    // ---------- transformer (L=2) ----------
    for (int l = 0; l < 2; l++) {
        gemm_mma<false><<<dim3(DDm/128, TPR/128), 256, GSMEM>>>(
            p_h, BH(oWq[l]), BL(oWq[l], DDm, DDm), DDm,
            nullptr, nullptr, nullptr, 0, nullptr, bq + l*DDm, p_q, TPR, DDm);
        gemm_mma<false><<<dim3(DDm/128, TPR/128), 256, GSMEM>>>(
            p_h, BH(oWk[l]), BL(oWk[l], DDm, DDm), DDm,
            nullptr, nullptr, nullptr, 0, nullptr, bk + l*DDm, p_k, TPR, DDm);
        gemm_mma<false><<<dim3(DDm/128, TPR/128), 256, GSMEM>>>(
            p_h, BH(oWv[l]), BL(oWv[l], DDm, DDm), DDm,
            nullptr, nullptr, nullptr, 0, nullptr, bv + l*DDm, p_v, TPR, DDm);

        k_attn<<<dim3(PP, 8), 64>>>();

        gemm_mma<false><<<dim3(DDm/128, TPR/128), 256, GSMEM>>>(
            p_o, BH(oWo[l]), BL(oWo[l], DDm, DDm), DDm,
            nullptr, nullptr, nullptr, 0, nullptr, bo + l*DDm, p_proj, TPR, DDm);
        k_ln<<<TPR/8, 256>>>(p_proj, g1 + l*DDm, bg1 + l*DDm);

        gemm_mma<true><<<dim3(FFD/128, TPR/128), 256, GSMEM>>>(
            p_h, BH(oWf1[l]), BL(oWf1[l], DDm, FFD), DDm,
            nullptr, nullptr, nullptr, 0, nullptr, bf1 + l*FFD, p_ff, TPR, FFD);
        gemm_mma<false><<<dim3(DDm/128, TPR/128), 256, GSMEM>>>(
            p_ff, BH(oWf2[l]), BL(oWf2[l], FFD, DDm), FFD,
            nullptr, nullptr, nullptr, 0, nullptr, bf2 + l*DDm, p_proj, TPR, DDm);
        k_ln<<<TPR/8, 256>>>(p_proj, g2 + l*DDm, bg2 + l*DDm);
    }

    k_out<<<TPR/8, 256>>>(Wout, out + (size_t)TPR * DDm);
}

// round 6
// speedup vs baseline: 2.8362x; 1.2026x over previous
#include <cuda_runtime.h>
#include <cuda_bf16.h>
#include <math.h>
#include <stdint.h>

#define NN   20000
#define EE   320000
#define TT   16
#define PP   4096
#define DIN  128
#define HH   256
#define DDm  512
#define FFD  2048
#define TPR  (TT*PP)   // 65536
#define MB   (TT*NN)   // 320000 batched rows

// ---------------- scratch (static device globals; no allocation) ----------------
__device__ int   g_cnt   [MB];
__device__ int   g_rowptr[MB];
__device__ int   g_cursor[MB];
__device__ int   g_eidx  [TT*EE];
__device__ float g_aggB[(size_t)MB*HH];
__device__ float g_h1B [(size_t)MB*HH];
__device__ float g_h2B [(size_t)MB*HH];
__device__ float g_h   [(size_t)TPR*DDm];
__device__ float g_qkv [(size_t)TPR*1536];
__device__ float g_o   [(size_t)TPR*DDm];
__device__ float g_proj[(size_t)TPR*DDm];
__device__ float g_ff  [(size_t)TPR*FFD];
__device__ float g_bqkv[2*1536];
__device__ __nv_bfloat16 g_w[12976128];

// ---------------- helpers ----------------
__device__ __forceinline__ uint32_t smem_u32(const void* p) {
    uint32_t a;
    asm("{ .reg .u64 t; cvta.to.shared.u64 t, %1; cvt.u32.u64 %0, t; }" : "=r"(a) : "l"(p));
    return a;
}
__device__ __forceinline__ void ldsm4(uint32_t* r, uint32_t addr) {
    asm volatile("ldmatrix.sync.aligned.m8n8.x4.shared.b16 {%0,%1,%2,%3}, [%4];"
                 : "=r"(r[0]), "=r"(r[1]), "=r"(r[2]), "=r"(r[3]) : "r"(addr));
}
__device__ __forceinline__ void mma16816(float* c, const uint32_t* a, const uint32_t* b) {
    asm volatile("mma.sync.aligned.m16n8k16.row.col.f32.bf16.bf16.f32 "
                 "{%0,%1,%2,%3}, {%4,%5,%6,%7}, {%8,%9}, {%0,%1,%2,%3};"
                 : "+f"(c[0]), "+f"(c[1]), "+f"(c[2]), "+f"(c[3])
                 : "r"(a[0]), "r"(a[1]), "r"(a[2]), "r"(a[3]), "r"(b[0]), "r"(b[1]));
}
__device__ __forceinline__ uint32_t pack2(float a, float b) {
    __nv_bfloat162 t = __floats2bfloat162_rn(a, b);
    return *reinterpret_cast<uint32_t*>(&t);
}

// smem geometry: rows of 32 bf16 padded to 80 bytes (conflict-free ldmatrix)
#define RSTR  80
#define MATB  (128*RSTR)
#define BUFB  (4*MATB)
#define GSMEM (2*BUFB)     // 81920

// ---------------- HMMA GEMM: C = A1@W1 (+ rowscale(A2)@W2) + bias, opt ReLU ------
template<bool RELU>
__global__ void __launch_bounds__(256)
gemm_mma(const float* __restrict__ A1, const __nv_bfloat16* __restrict__ B1h,
         const __nv_bfloat16* __restrict__ B1l, int K1,
         const float* __restrict__ A2, const __nv_bfloat16* __restrict__ B2h,
         const __nv_bfloat16* __restrict__ B2l, int K2,
         const float* __restrict__ rs2,
         const float* __restrict__ bias, float* __restrict__ C, int M, int N) {
    extern __shared__ char smb[];
    const uint32_t sb = smem_u32(smb);
    const int tid = threadIdx.x, lane = tid & 31, wid = tid >> 5;
    const int bRow = blockIdx.y * 128, bCol = blockIdx.x * 128;
    const int wm = wid & 3, wn = wid >> 2;
    const int lrow = tid >> 1, lhalf = tid & 1;

    const int nc1 = K1 >> 5;
    const int nc  = nc1 + (K2 >> 5);

    float acc[2][8][4];
#pragma unroll
    for (int i = 0; i < 2; i++)
#pragma unroll
        for (int j = 0; j < 8; j++)
#pragma unroll
            for (int q = 0; q < 4; q++) acc[i][j][q] = 0.f;

    float a_st[16];
    uint4 bh_st[2], bl_st[2];

#define GLOAD(cc) do {                                                          \
    const float* A_; const __nv_bfloat16 *Bh_, *Bl_; int K_, k0_; bool sc_;     \
    if ((cc) < nc1) { A_ = A1; Bh_ = B1h; Bl_ = B1l; K_ = K1; k0_ = (cc) << 5;  \
                      sc_ = false; }                                            \
    else { A_ = A2; Bh_ = B2h; Bl_ = B2l; K_ = K2; k0_ = ((cc) - nc1) << 5;     \
           sc_ = (rs2 != nullptr); }                                            \
    const int grow_ = bRow + lrow;                                              \
    if (grow_ < M) {                                                            \
        const float* ap_ = A_ + (size_t)grow_ * K_ + k0_ + lhalf * 16;          \
        *(float4*)(a_st + 0)  = ((const float4*)ap_)[0];                        \
        *(float4*)(a_st + 4)  = ((const float4*)ap_)[1];                        \
        *(float4*)(a_st + 8)  = ((const float4*)ap_)[2];                        \
        *(float4*)(a_st + 12) = ((const float4*)ap_)[3];                        \
        if (sc_) {                                                              \
            float iv_ = 1.0f / fmaxf(rs2[grow_], 1.0f);                         \
            _Pragma("unroll") for (int j_ = 0; j_ < 16; j_++) a_st[j_] *= iv_;  \
        }                                                                       \
    } else {                                                                    \
        _Pragma("unroll") for (int j_ = 0; j_ < 16; j_++) a_st[j_] = 0.f;       \
    }                                                                           \
    const size_t bo_ = (size_t)(bCol + lrow) * K_ + k0_ + lhalf * 16;           \
    bh_st[0] = ((const uint4*)(Bh_ + bo_))[0];                                  \
    bh_st[1] = ((const uint4*)(Bh_ + bo_))[1];                                  \
    bl_st[0] = ((const uint4*)(Bl_ + bo_))[0];                                  \
    bl_st[1] = ((const uint4*)(Bl_ + bo_))[1];                                  \
} while (0)

#define SSTORE(buf) do {                                                        \
    char* base_ = smb + (buf) * BUFB;                                          \
    const uint32_t ro_ = lrow * RSTR + lhalf * 32;                              \
    uint32_t hi_[8], lo_[8];                                                    \
    _Pragma("unroll") for (int j_ = 0; j_ < 8; j_++) {                          \
        float f0_ = a_st[2*j_], f1_ = a_st[2*j_+1];                             \
        __nv_bfloat16 h0_ = __float2bfloat16(f0_), h1_ = __float2bfloat16(f1_); \
        float v0_ = __bfloat162float(h0_), v1_ = __bfloat162float(h1_);         \
        hi_[j_] = pack2(v0_, v1_);                                              \
        lo_[j_] = pack2(f0_ - v0_, f1_ - v1_);                                  \
    }                                                                           \
    *(uint4*)(base_ + ro_)             = make_uint4(hi_[0],hi_[1],hi_[2],hi_[3]);\
    *(uint4*)(base_ + ro_ + 16)        = make_uint4(hi_[4],hi_[5],hi_[6],hi_[7]);\
    *(uint4*)(base_ + MATB + ro_)      = make_uint4(lo_[0],lo_[1],lo_[2],lo_[3]);\
    *(uint4*)(base_ + MATB + ro_ + 16) = make_uint4(lo_[4],lo_[5],lo_[6],lo_[7]);\
    *(uint4*)(base_ + 2*MATB + ro_)      = bh_st[0];                            \
    *(uint4*)(base_ + 2*MATB + ro_ + 16) = bh_st[1];                            \
    *(uint4*)(base_ + 3*MATB + ro_)      = bl_st[0];                            \
    *(uint4*)(base_ + 3*MATB + ro_ + 16) = bl_st[1];                            \
} while (0)

#define COMPUTE(buf) do {                                                       \
    const uint32_t ah_ = sb + (buf) * BUFB;                                     \
    const uint32_t al_ = ah_ + MATB, bhp_ = ah_ + 2*MATB, blp_ = ah_ + 3*MATB;  \
    _Pragma("unroll") for (int ks_ = 0; ks_ < 2; ks_++) {                       \
        uint32_t aH_[2][4], aL_[2][4], bH_[4][4], bL_[4][4];                    \
        const int arow_ = wm * 32 + (lane & 15);                                \
        const int acol_ = ks_ * 32 + ((lane >> 4) << 4);                        \
        ldsm4(aH_[0], ah_ + arow_ * RSTR + acol_);                              \
        ldsm4(aH_[1], ah_ + (arow_ + 16) * RSTR + acol_);                       \
        ldsm4(aL_[0], al_ + arow_ * RSTR + acol_);                              \
        ldsm4(aL_[1], al_ + (arow_ + 16) * RSTR + acol_);                       \
        const int br_ = lane & 7, bg_ = lane >> 3;                              \
        const int brow_ = wn * 64 + ((bg_ >> 1) << 3) + br_;                    \
        const int bcol_ = ks_ * 32 + ((bg_ & 1) << 4);                          \
        _Pragma("unroll") for (int nj_ = 0; nj_ < 4; nj_++) {                   \
            ldsm4(bH_[nj_], bhp_ + (brow_ + nj_ * 16) * RSTR + bcol_);          \
            ldsm4(bL_[nj_], blp_ + (brow_ + nj_ * 16) * RSTR + bcol_);          \
        }                                                                       \
        _Pragma("unroll") for (int mi_ = 0; mi_ < 2; mi_++)                     \
        _Pragma("unroll") for (int ni_ = 0; ni_ < 8; ni_++) {                   \
            const uint32_t* bh2_ = &bH_[ni_ >> 1][(ni_ & 1) * 2];               \
            const uint32_t* bl2_ = &bL_[ni_ >> 1][(ni_ & 1) * 2];               \
            mma16816(acc[mi_][ni_], aH_[mi_], bh2_);                            \
            mma16816(acc[mi_][ni_], aH_[mi_], bl2_);                            \
            mma16816(acc[mi_][ni_], aL_[mi_], bh2_);                            \
        }                                                                       \
    }                                                                           \
} while (0)

    GLOAD(0);
    SSTORE(0);
    __syncthreads();
    for (int c = 0; c < nc; c++) {
        if (c + 1 < nc) GLOAD(c + 1);
        COMPUTE(c & 1);
        if (c + 1 < nc) SSTORE((c + 1) & 1);
        __syncthreads();
    }

#pragma unroll
    for (int mi = 0; mi < 2; mi++) {
        const int r0 = bRow + wm * 32 + mi * 16 + (lane >> 2);
#pragma unroll
        for (int ni = 0; ni < 8; ni++) {
            const int col = bCol + wn * 64 + ni * 8 + (lane & 3) * 2;
            const float b0 = bias[col], b1 = bias[col + 1];
            if (r0 < M) {
                float c0 = acc[mi][ni][0] + b0, c1 = acc[mi][ni][1] + b1;
                if (RELU) { c0 = fmaxf(c0, 0.f); c1 = fmaxf(c1, 0.f); }
                *(float2*)(C + (size_t)r0 * N + col) = make_float2(c0, c1);
            }
            if (r0 + 8 < M) {
                float c2 = acc[mi][ni][2] + b0, c3 = acc[mi][ni][3] + b1;
                if (RELU) { c2 = fmaxf(c2, 0.f); c3 = fmaxf(c3, 0.f); }
                *(float2*)(C + (size_t)(r0 + 8) * N + col) = make_float2(c2, c3);
            }
        }
    }
#undef GLOAD
#undef SSTORE
#undef COMPUTE
}

// ---------------- weight prep: W[K][N] fp32 -> Th/Tl [N][K] bf16 ----------------
__global__ void k_wprep(const float* __restrict__ W, __nv_bfloat16* __restrict__ Th,
                        __nv_bfloat16* __restrict__ Tl, int K, int N) {
    __shared__ float s[32][33];
    int n0 = blockIdx.x * 32, k0 = blockIdx.y * 32;
    for (int r = threadIdx.y; r < 32; r += 8)
        s[r][threadIdx.x] = W[(size_t)(k0 + r) * N + n0 + threadIdx.x];
    __syncthreads();
    for (int r = threadIdx.y; r < 32; r += 8) {
        float f = s[threadIdx.x][r];
        __nv_bfloat16 hb = __float2bfloat16(f);
        float hv = __bfloat162float(hb);
        size_t o = (size_t)(n0 + r) * K + k0 + threadIdx.x;
        Th[o] = hb;
        Tl[o] = __float2bfloat16(f - hv);
    }
}

// ---------------- CSR build ----------------
__global__ void k_zeroi(int* __restrict__ p, unsigned n) {
    unsigned i = blockIdx.x * blockDim.x + threadIdx.x;
    if (i < n) p[i] = 0;
}
__global__ void k_count(const int* __restrict__ dst, int* __restrict__ cnt) {
    unsigned e = blockIdx.x * blockDim.x + threadIdx.x;
    if (e >= TT * EE) return;
    int t = e / EE;
    atomicAdd(&cnt[t * NN + dst[e]], 1);
}
// per-timestep exclusive scan (block per t); each timestep owns exactly EE edges
__global__ void k_scan(const int* __restrict__ cnt, int* __restrict__ rowptr,
                       int* __restrict__ cursor) {
    int t = blockIdx.x;
    __shared__ int sdata[1024];
    __shared__ int carry_s;
    if (threadIdx.x == 0) carry_s = t * EE;
    __syncthreads();
    for (int c0 = 0; c0 < NN; c0 += 1024) {
        int i = c0 + threadIdx.x;
        int v = (i < NN) ? cnt[t * NN + i] : 0;
        sdata[threadIdx.x] = v;
        __syncthreads();
        for (int off = 1; off < 1024; off <<= 1) {
            int add = (threadIdx.x >= (unsigned)off) ? sdata[threadIdx.x - off] : 0;
            __syncthreads();
            sdata[threadIdx.x] += add;
            __syncthreads();
        }
        int excl = sdata[threadIdx.x] - v;
        if (i < NN) {
            int r = carry_s + excl;
            rowptr[t * NN + i] = r;
            cursor[t * NN + i] = r;
        }
        __syncthreads();
        if (threadIdx.x == 0) carry_s += sdata[1023];
        __syncthreads();
    }
}
__global__ void k_fill(const int* __restrict__ src, const int* __restrict__ dst,
                       int* __restrict__ cursor, int* __restrict__ eidx) {
    unsigned e = blockIdx.x * blockDim.x + threadIdx.x;
    if (e >= TT * EE) return;
    int t = e / EE;
    int pos = atomicAdd(&cursor[t * NN + dst[e]], 1);
    eidx[pos] = t * NN + src[e];
}
// CSR mean-aggregate: warp per node row; F = F4PL*128 floats
template<int F4PL>
__global__ void k_agg(const float* __restrict__ x, const int* __restrict__ rowptr,
                      const int* __restrict__ cnt, const int* __restrict__ eidx,
                      float* __restrict__ agg) {
    int w = threadIdx.x >> 5, lane = threadIdx.x & 31;
    unsigned n = blockIdx.x * 8 + w;
    if (n >= MB) return;
    const int F = F4PL * 128;
    int beg = rowptr[n], c = cnt[n];
    float4 acc[F4PL];
#pragma unroll
    for (int j = 0; j < F4PL; j++) acc[j] = make_float4(0.f, 0.f, 0.f, 0.f);
    int i = 0;
    for (; i + 1 < c; i += 2) {
        int s0 = eidx[beg + i], s1 = eidx[beg + i + 1];
        const float4* r0 = (const float4*)(x + (size_t)s0 * F);
        const float4* r1 = (const float4*)(x + (size_t)s1 * F);
#pragma unroll
        for (int j = 0; j < F4PL; j++) {
            float4 a = r0[lane + 32 * j], b = r1[lane + 32 * j];
            acc[j].x += a.x + b.x; acc[j].y += a.y + b.y;
            acc[j].z += a.z + b.z; acc[j].w += a.w + b.w;
        }
    }
    if (i < c) {
        const float4* r0 = (const float4*)(x + (size_t)eidx[beg + i] * F);
#pragma unroll
        for (int j = 0; j < F4PL; j++) {
            float4 a = r0[lane + 32 * j];
            acc[j].x += a.x; acc[j].y += a.y; acc[j].z += a.z; acc[j].w += a.w;
        }
    }
    float sc = 1.0f / (float)(c > 0 ? c : 1);
    float4* dst = (float4*)(agg + (size_t)n * F);
#pragma unroll
    for (int j = 0; j < F4PL; j++) {
        acc[j].x *= sc; acc[j].y *= sc; acc[j].z *= sc; acc[j].w *= sc;
        dst[lane + 32 * j] = acc[j];
    }
}

// ---------------- misc kernels ----------------
__global__ void k_normgather(const float* __restrict__ h2, const int* __restrict__ idx,
                             float* __restrict__ att_out, float* __restrict__ hbuf, int off) {
    int w = threadIdx.x >> 5, lane = threadIdx.x & 31;
    unsigned tp = blockIdx.x * 8 + w;
    int t = tp >> 12, p = tp & 4095;
    int n = idx[t * PP + p];
    const float* row = h2 + ((size_t)t * NN + n) * HH;
    float v[8]; float ss = 0.f;
#pragma unroll
    for (int i = 0; i < 8; i++) { v[i] = row[lane + i * 32]; ss += v[i] * v[i]; }
#pragma unroll
    for (int o = 16; o; o >>= 1) ss += __shfl_xor_sync(0xffffffffu, ss, o);
    float inv = 1.0f / fmaxf(sqrtf(ss), 1e-12f);
    size_t o0 = (size_t)tp * DDm + off;
#pragma unroll
    for (int i = 0; i < 8; i++) {
        float val = v[i] * inv;
        att_out[o0 + lane + i * 32] = val;
        hbuf[o0 + lane + i * 32] = val;
    }
}
__global__ void k_attn(const float* __restrict__ qkv) {
    int p = blockIdx.x, h = blockIdx.y;
    int tid = threadIdx.x;
    __shared__ float qs[TT][64], ks[TT][64], vs[TT][64];
    __shared__ float att[TT][4];
    size_t base = (size_t)p * 1536 + h * 64 + tid;
#pragma unroll
    for (int t = 0; t < TT; t++) {
        size_t off = (size_t)t * PP * 1536 + base;
        qs[t][tid] = qkv[off];
        ks[t][tid] = qkv[off + 512];
        vs[t][tid] = qkv[off + 1024];
    }
    __syncthreads();
    {
        int t = tid >> 2, j = tid & 3, s = t - j;
        float sc = -INFINITY;
        if (s >= 0) {
            float a = 0.f;
#pragma unroll
            for (int d = 0; d < 64; d++) a += qs[t][d] * ks[s][d];
            sc = a * 0.125f;
        }
        att[t][j] = sc;
    }
    __syncthreads();
    if (tid < TT) {
        float m = -INFINITY;
#pragma unroll
        for (int j = 0; j < 4; j++) m = fmaxf(m, att[tid][j]);
        float sum = 0.f, e[4];
#pragma unroll
        for (int j = 0; j < 4; j++) {
            float x = att[tid][j];
            float ee = (x == -INFINITY) ? 0.f : expf(x - m);
            e[j] = ee; sum += ee;
        }
        float inv = 1.0f / sum;
#pragma unroll
        for (int j = 0; j < 4; j++) att[tid][j] = e[j] * inv;
    }
    __syncthreads();
    size_t obase = (size_t)p * DDm + h * 64 + tid;
#pragma unroll
    for (int t = 0; t < TT; t++) {
        float a = 0.f;
#pragma unroll
        for (int j = 0; j < 4; j++) {
            int s = t - j;
            if (s >= 0) a += att[t][j] * vs[s][tid];
        }
        g_o[(size_t)t * PP * DDm + obase] = a;
    }
}
__global__ void k_ln(const float* __restrict__ r, const float* __restrict__ g,
                     const float* __restrict__ b) {
    int w = threadIdx.x >> 5, lane = threadIdx.x & 31;
    size_t row = (size_t)blockIdx.x * 8 + w;
    float* xr = g_h + row * DDm;
    const float* rr = r + row * DDm;
    float v[16]; float s = 0.f;
#pragma unroll
    for (int i = 0; i < 16; i++) {
        int c = lane + i * 32;
        float t = xr[c] + rr[c];
        v[i] = t; s += t;
    }
#pragma unroll
    for (int o = 16; o; o >>= 1) s += __shfl_xor_sync(0xffffffffu, s, o);
    float mean = s * (1.0f / DDm);
    float vs = 0.f;
#pragma unroll
    for (int i = 0; i < 16; i++) { float d = v[i] - mean; vs += d * d; }
#pragma unroll
    for (int o = 16; o; o >>= 1) vs += __shfl_xor_sync(0xffffffffu, vs, o);
    float inv = rsqrtf(vs * (1.0f / DDm) + 1e-5f);
#pragma unroll
    for (int i = 0; i < 16; i++) {
        int c = lane + i * 32;
        xr[c] = (v[i] - mean) * inv * g[c] + b[c];
    }
}
__global__ void k_out(const float* __restrict__ wout, float* __restrict__ out) {
    int w = threadIdx.x >> 5, lane = threadIdx.x & 31;
    size_t row = (size_t)blockIdx.x * 8 + w;
    const float* hr = g_h + row * DDm;
    float s = 0.f;
#pragma unroll
    for (int i = 0; i < 16; i++) { int c = lane + i * 32; s += hr[c] * wout[c]; }
#pragma unroll
    for (int o = 16; o; o >>= 1) s += __shfl_xor_sync(0xffffffffu, s, o);
    if (lane == 0) out[row] = s;
}

// =======================================================================================
extern "C" void kernel_launch(void* const* d_in, const int* in_sizes, int n_in,
                              void* d_out, int out_size) {
    const float* x_i  = (const float*)d_in[0];
    const float* x_j  = (const float*)d_in[1];
    const int* src_i  = (const int*)d_in[2];
    const int* dst_i  = (const int*)d_in[3];
    const int* src_j  = (const int*)d_in[4];
    const int* dst_j  = (const int*)d_in[5];
    const int* idx_i  = (const int*)d_in[6];
    const int* idx_j  = (const int*)d_in[7];
    const float* W1s  = (const float*)d_in[8];
    const float* W1n  = (const float*)d_in[9];
    const float* b1   = (const float*)d_in[10];
    const float* W2s  = (const float*)d_in[11];
    const float* W2n  = (const float*)d_in[12];
    const float* b2   = (const float*)d_in[13];
    const float* Wq   = (const float*)d_in[14];
    const float* Wk   = (const float*)d_in[15];
    const float* Wv   = (const float*)d_in[16];
    const float* bq   = (const float*)d_in[17];
    const float* bk   = (const float*)d_in[18];
    const float* bv   = (const float*)d_in[19];
    const float* Wo   = (const float*)d_in[20];
    const float* bo   = (const float*)d_in[21];
    const float* Wf1  = (const float*)d_in[22];
    const float* bf1  = (const float*)d_in[23];
    const float* Wf2  = (const float*)d_in[24];
    const float* bf2  = (const float*)d_in[25];
    const float* g1   = (const float*)d_in[26];
    const float* bg1  = (const float*)d_in[27];
    const float* g2   = (const float*)d_in[28];
    const float* bg2  = (const float*)d_in[29];
    const float* Wout = (const float*)d_in[30];
    float* out = (float*)d_out;

    float *p_aggB, *p_h1B, *p_h2B, *p_h, *p_qkv, *p_o, *p_proj, *p_ff, *p_bqkv;
    int *p_cnt, *p_rowptr, *p_cursor, *p_eidx;
    __nv_bfloat16* p_w;
    cudaGetSymbolAddress((void**)&p_cnt,    g_cnt);
    cudaGetSymbolAddress((void**)&p_rowptr, g_rowptr);
    cudaGetSymbolAddress((void**)&p_cursor, g_cursor);
    cudaGetSymbolAddress((void**)&p_eidx,   g_eidx);
    cudaGetSymbolAddress((void**)&p_aggB,   g_aggB);
    cudaGetSymbolAddress((void**)&p_h1B,    g_h1B);
    cudaGetSymbolAddress((void**)&p_h2B,    g_h2B);
    cudaGetSymbolAddress((void**)&p_h,      g_h);
    cudaGetSymbolAddress((void**)&p_qkv,    g_qkv);
    cudaGetSymbolAddress((void**)&p_o,      g_o);
    cudaGetSymbolAddress((void**)&p_proj,   g_proj);
    cudaGetSymbolAddress((void**)&p_ff,     g_ff);
    cudaGetSymbolAddress((void**)&p_bqkv,   g_bqkv);
    cudaGetSymbolAddress((void**)&p_w,      g_w);

    cudaFuncSetAttribute(gemm_mma<false>, cudaFuncAttributeMaxDynamicSharedMemorySize, GSMEM);
    cudaFuncSetAttribute(gemm_mma<true>,  cudaFuncAttributeMaxDynamicSharedMemorySize, GSMEM);

    // ---- weight prep ----
    size_t off = 0;
    auto prep = [&](const float* W, int K, int N) -> size_t {
        size_t b = off;
        k_wprep<<<dim3(N/32, K/32), dim3(32, 8)>>>(W, p_w + b, p_w + b + (size_t)K*N, K, N);
        off += 2 * (size_t)K * N;
        return b;
    };
    size_t oW1s = prep(W1s, DIN, HH), oW1n = prep(W1n, DIN, HH);
    size_t oW2s = prep(W2s, HH, HH),  oW2n = prep(W2n, HH, HH);
    // fused QKV: Th rows [q|k|v] (1536 x 512), then Tl
    size_t oQKV[2];
    for (int l = 0; l < 2; l++) {
        size_t b = off; off += 2 * (size_t)1536 * DDm;
        const size_t KN = (size_t)DDm * DDm, LO = (size_t)1536 * DDm;
        k_wprep<<<dim3(DDm/32, DDm/32), dim3(32, 8)>>>(Wq + (size_t)l*KN, p_w + b,          p_w + b + LO,          DDm, DDm);
        k_wprep<<<dim3(DDm/32, DDm/32), dim3(32, 8)>>>(Wk + (size_t)l*KN, p_w + b + KN,     p_w + b + LO + KN,     DDm, DDm);
        k_wprep<<<dim3(DDm/32, DDm/32), dim3(32, 8)>>>(Wv + (size_t)l*KN, p_w + b + 2*KN,   p_w + b + LO + 2*KN,   DDm, DDm);
        oQKV[l] = b;
    }
    size_t oWo[2], oWf1[2], oWf2[2];
    for (int l = 0; l < 2; l++) {
        oWo[l]  = prep(Wo  + (size_t)l*DDm*DDm, DDm, DDm);
        oWf1[l] = prep(Wf1 + (size_t)l*DDm*FFD, DDm, FFD);
        oWf2[l] = prep(Wf2 + (size_t)l*FFD*DDm, FFD, DDm);
    }
    auto BH = [&](size_t b) { return p_w + b; };
    auto BL = [&](size_t b, size_t K, size_t N) { return p_w + b + K * N; };

    // concatenated QKV bias
    for (int l = 0; l < 2; l++) {
        cudaMemcpyAsync(p_bqkv + l*1536,        bq + l*DDm, DDm*4, cudaMemcpyDeviceToDevice);
        cudaMemcpyAsync(p_bqkv + l*1536 + 512,  bk + l*DDm, DDm*4, cudaMemcpyDeviceToDevice);
        cudaMemcpyAsync(p_bqkv + l*1536 + 1024, bv + l*DDm, DDm*4, cudaMemcpyDeviceToDevice);
    }

    // ---------- GraphSAGE: batched over TT timesteps, CSR-gather aggregation ----------
    for (int gsel = 0; gsel < 2; gsel++) {
        const float* x  = gsel ? x_j   : x_i;
        const int* src  = gsel ? src_j : src_i;
        const int* dstp = gsel ? dst_j : dst_i;
        const int* idx  = gsel ? idx_j : idx_i;

        // CSR build (once per graph; reused by both layers)
        k_zeroi<<<(MB + 255)/256, 256>>>(p_cnt, MB);
        k_count<<<(TT*EE + 255)/256, 256>>>(dstp, p_cnt);
        k_scan <<<TT, 1024>>>(p_cnt, p_rowptr, p_cursor);
        k_fill <<<(TT*EE + 255)/256, 256>>>(src, dstp, p_cursor, p_eidx);

        // layer 1: gather-mean x (F=128), dual GEMM -> h1B
        k_agg<1><<<(MB + 7)/8, 256>>>(x, p_rowptr, p_cnt, p_eidx, p_aggB);
        gemm_mma<true><<<dim3(HH/128, (MB + 127)/128), 256, GSMEM>>>(
            x, BH(oW1s), BL(oW1s, DIN, HH), DIN,
            p_aggB, BH(oW1n), BL(oW1n, DIN, HH), DIN, nullptr, b1, p_h1B, MB, HH);

        // layer 2: gather-mean h1 (F=256), dual GEMM -> h2B
        k_agg<2><<<(MB + 7)/8, 256>>>(p_h1B, p_rowptr, p_cnt, p_eidx, p_aggB);
        gemm_mma<false><<<dim3(HH/128, (MB + 127)/128), 256, GSMEM>>>(
            p_h1B, BH(oW2s), BL(oW2s, HH, HH), HH,
            p_aggB, BH(oW2n), BL(oW2n, HH, HH), HH, nullptr, b2, p_h2B, MB, HH);

        k_normgather<<<TPR/8, 256>>>(p_h2B, idx, out, p_h, gsel * HH);
    }

    // ---------- transformer (L=2) ----------
    for (int l = 0; l < 2; l++) {
        // fused QKV projection: [TPR,512] @ [512,1536]
        gemm_mma<false><<<dim3(1536/128, TPR/128), 256, GSMEM>>>(
            p_h, BH(oQKV[l]), BL(oQKV[l], 1536, DDm), DDm,
            nullptr, nullptr, nullptr, 0, nullptr, p_bqkv + l*1536, p_qkv, TPR, 1536);

        k_attn<<<dim3(PP, 8), 64>>>(p_qkv);

        gemm_mma<false><<<dim3(DDm/128, TPR/128), 256, GSMEM>>>(
            p_o, BH(oWo[l]), BL(oWo[l], DDm, DDm), DDm,
            nullptr, nullptr, nullptr, 0, nullptr, bo + l*DDm, p_proj, TPR, DDm);
        k_ln<<<TPR/8, 256>>>(p_proj, g1 + l*DDm, bg1 + l*DDm);

        gemm_mma<true><<<dim3(FFD/128, TPR/128), 256, GSMEM>>>(
            p_h, BH(oWf1[l]), BL(oWf1[l], DDm, FFD), DDm,
            nullptr, nullptr, nullptr, 0, nullptr, bf1 + l*FFD, p_ff, TPR, FFD);
        gemm_mma<false><<<dim3(DDm/128, TPR/128), 256, GSMEM>>>(
            p_ff, BH(oWf2[l]), BL(oWf2[l], FFD, DDm), FFD,
            nullptr, nullptr, nullptr, 0, nullptr, bf2 + l*DDm, p_proj, TPR, DDm);
        k_ln<<<TPR/8, 256>>>(p_proj, g2 + l*DDm, bg2 + l*DDm);
    }

    k_out<<<TPR/8, 256>>>(Wout, out + (size_t)TPR * DDm);
}

// round 7
// speedup vs baseline: 2.8956x; 1.0209x over previous
#include <cuda_runtime.h>
#include <cuda_bf16.h>
#include <math.h>
#include <stdint.h>

#define NN   20000
#define EE   320000
#define TT   16
#define PP   4096
#define DIN  128
#define HH   256
#define DDm  512
#define FFD  2048
#define TPR  (TT*PP)   // 65536
#define MB   (TT*NN)   // 320000 batched rows

// ---------------- scratch (static device globals; no allocation) ----------------
// per-graph duplicated SAGE scratch (index 0 = graph i, 1 = graph j)
__device__ int   g_cnt   [2*MB];
__device__ int   g_rowptr[2*MB];
__device__ int   g_cursor[2*MB];
__device__ int   g_eidx  [2*TT*EE];
__device__ float g_aggB[(size_t)2*MB*HH];
__device__ float g_h1B [(size_t)2*MB*HH];
__device__ float g_h2B [(size_t)2*MB*HH];
__device__ float g_h   [(size_t)TPR*DDm];
__device__ float g_qkv [(size_t)TPR*1536];
__device__ float g_o   [(size_t)TPR*DDm];
__device__ float g_proj[(size_t)TPR*DDm];
__device__ float g_ff  [(size_t)TPR*FFD];
__device__ float g_bqkv[2*1536];
__device__ __nv_bfloat16 g_w[12976128];

// ---------------- helpers ----------------
__device__ __forceinline__ uint32_t smem_u32(const void* p) {
    uint32_t a;
    asm("{ .reg .u64 t; cvta.to.shared.u64 t, %1; cvt.u32.u64 %0, t; }" : "=r"(a) : "l"(p));
    return a;
}
__device__ __forceinline__ void ldsm4(uint32_t* r, uint32_t addr) {
    asm volatile("ldmatrix.sync.aligned.m8n8.x4.shared.b16 {%0,%1,%2,%3}, [%4];"
                 : "=r"(r[0]), "=r"(r[1]), "=r"(r[2]), "=r"(r[3]) : "r"(addr));
}
__device__ __forceinline__ void mma16816(float* c, const uint32_t* a, const uint32_t* b) {
    asm volatile("mma.sync.aligned.m16n8k16.row.col.f32.bf16.bf16.f32 "
                 "{%0,%1,%2,%3}, {%4,%5,%6,%7}, {%8,%9}, {%0,%1,%2,%3};"
                 : "+f"(c[0]), "+f"(c[1]), "+f"(c[2]), "+f"(c[3])
                 : "r"(a[0]), "r"(a[1]), "r"(a[2]), "r"(a[3]), "r"(b[0]), "r"(b[1]));
}
__device__ __forceinline__ uint32_t pack2(float a, float b) {
    __nv_bfloat162 t = __floats2bfloat162_rn(a, b);
    return *reinterpret_cast<uint32_t*>(&t);
}

// smem geometry: rows of 32 bf16 padded to 80 bytes (conflict-free ldmatrix)
#define RSTR  80
#define MATB  (128*RSTR)
#define BUFB  (4*MATB)
#define GSMEM (2*BUFB)     // 81920

// ---------------- HMMA GEMM: C = A1@W1 (+ A2@W2) + bias, opt ReLU ------
template<bool RELU>
__global__ void __launch_bounds__(256)
gemm_mma(const float* __restrict__ A1, const __nv_bfloat16* __restrict__ B1h,
         const __nv_bfloat16* __restrict__ B1l, int K1,
         const float* __restrict__ A2, const __nv_bfloat16* __restrict__ B2h,
         const __nv_bfloat16* __restrict__ B2l, int K2,
         const float* __restrict__ bias, float* __restrict__ C, int M, int N) {
    extern __shared__ char smb[];
    const uint32_t sb = smem_u32(smb);
    const int tid = threadIdx.x, lane = tid & 31, wid = tid >> 5;
    const int bRow = blockIdx.y * 128, bCol = blockIdx.x * 128;
    const int wm = wid & 3, wn = wid >> 2;
    const int lrow = tid >> 1, lhalf = tid & 1;

    const int nc1 = K1 >> 5;
    const int nc  = nc1 + (K2 >> 5);

    float acc[2][8][4];
#pragma unroll
    for (int i = 0; i < 2; i++)
#pragma unroll
        for (int j = 0; j < 8; j++)
#pragma unroll
            for (int q = 0; q < 4; q++) acc[i][j][q] = 0.f;

    float a_st[16];
    uint4 bh_st[2], bl_st[2];

#define GLOAD(cc) do {                                                          \
    const float* A_; const __nv_bfloat16 *Bh_, *Bl_; int K_, k0_;               \
    if ((cc) < nc1) { A_ = A1; Bh_ = B1h; Bl_ = B1l; K_ = K1; k0_ = (cc) << 5; }\
    else { A_ = A2; Bh_ = B2h; Bl_ = B2l; K_ = K2; k0_ = ((cc) - nc1) << 5; }   \
    const int grow_ = bRow + lrow;                                              \
    if (grow_ < M) {                                                            \
        const float* ap_ = A_ + (size_t)grow_ * K_ + k0_ + lhalf * 16;          \
        *(float4*)(a_st + 0)  = ((const float4*)ap_)[0];                        \
        *(float4*)(a_st + 4)  = ((const float4*)ap_)[1];                        \
        *(float4*)(a_st + 8)  = ((const float4*)ap_)[2];                        \
        *(float4*)(a_st + 12) = ((const float4*)ap_)[3];                        \
    } else {                                                                    \
        _Pragma("unroll") for (int j_ = 0; j_ < 16; j_++) a_st[j_] = 0.f;       \
    }                                                                           \
    const size_t bo_ = (size_t)(bCol + lrow) * K_ + k0_ + lhalf * 16;           \
    bh_st[0] = ((const uint4*)(Bh_ + bo_))[0];                                  \
    bh_st[1] = ((const uint4*)(Bh_ + bo_))[1];                                  \
    bl_st[0] = ((const uint4*)(Bl_ + bo_))[0];                                  \
    bl_st[1] = ((const uint4*)(Bl_ + bo_))[1];                                  \
} while (0)

#define SSTORE(buf) do {                                                        \
    char* base_ = smb + (buf) * BUFB;                                          \
    const uint32_t ro_ = lrow * RSTR + lhalf * 32;                              \
    uint32_t hi_[8], lo_[8];                                                    \
    _Pragma("unroll") for (int j_ = 0; j_ < 8; j_++) {                          \
        float f0_ = a_st[2*j_], f1_ = a_st[2*j_+1];                             \
        __nv_bfloat16 h0_ = __float2bfloat16(f0_), h1_ = __float2bfloat16(f1_); \
        float v0_ = __bfloat162float(h0_), v1_ = __bfloat162float(h1_);         \
        hi_[j_] = pack2(v0_, v1_);                                              \
        lo_[j_] = pack2(f0_ - v0_, f1_ - v1_);                                  \
    }                                                                           \
    *(uint4*)(base_ + ro_)             = make_uint4(hi_[0],hi_[1],hi_[2],hi_[3]);\
    *(uint4*)(base_ + ro_ + 16)        = make_uint4(hi_[4],hi_[5],hi_[6],hi_[7]);\
    *(uint4*)(base_ + MATB + ro_)      = make_uint4(lo_[0],lo_[1],lo_[2],lo_[3]);\
    *(uint4*)(base_ + MATB + ro_ + 16) = make_uint4(lo_[4],lo_[5],lo_[6],lo_[7]);\
    *(uint4*)(base_ + 2*MATB + ro_)      = bh_st[0];                            \
    *(uint4*)(base_ + 2*MATB + ro_ + 16) = bh_st[1];                            \
    *(uint4*)(base_ + 3*MATB + ro_)      = bl_st[0];                            \
    *(uint4*)(base_ + 3*MATB + ro_ + 16) = bl_st[1];                            \
} while (0)

#define COMPUTE(buf) do {                                                       \
    const uint32_t ah_ = sb + (buf) * BUFB;                                     \
    const uint32_t al_ = ah_ + MATB, bhp_ = ah_ + 2*MATB, blp_ = ah_ + 3*MATB;  \
    _Pragma("unroll") for (int ks_ = 0; ks_ < 2; ks_++) {                       \
        uint32_t aH_[2][4], aL_[2][4], bH_[4][4], bL_[4][4];                    \
        const int arow_ = wm * 32 + (lane & 15);                                \
        const int acol_ = ks_ * 32 + ((lane >> 4) << 4);                        \
        ldsm4(aH_[0], ah_ + arow_ * RSTR + acol_);                              \
        ldsm4(aH_[1], ah_ + (arow_ + 16) * RSTR + acol_);                       \
        ldsm4(aL_[0], al_ + arow_ * RSTR + acol_);                              \
        ldsm4(aL_[1], al_ + (arow_ + 16) * RSTR + acol_);                       \
        const int br_ = lane & 7, bg_ = lane >> 3;                              \
        const int brow_ = wn * 64 + ((bg_ >> 1) << 3) + br_;                    \
        const int bcol_ = ks_ * 32 + ((bg_ & 1) << 4);                          \
        _Pragma("unroll") for (int nj_ = 0; nj_ < 4; nj_++) {                   \
            ldsm4(bH_[nj_], bhp_ + (brow_ + nj_ * 16) * RSTR + bcol_);          \
            ldsm4(bL_[nj_], blp_ + (brow_ + nj_ * 16) * RSTR + bcol_);          \
        }                                                                       \
        _Pragma("unroll") for (int mi_ = 0; mi_ < 2; mi_++)                     \
        _Pragma("unroll") for (int ni_ = 0; ni_ < 8; ni_++) {                   \
            const uint32_t* bh2_ = &bH_[ni_ >> 1][(ni_ & 1) * 2];               \
            const uint32_t* bl2_ = &bL_[ni_ >> 1][(ni_ & 1) * 2];               \
            mma16816(acc[mi_][ni_], aH_[mi_], bh2_);                            \
            mma16816(acc[mi_][ni_], aH_[mi_], bl2_);                            \
            mma16816(acc[mi_][ni_], aL_[mi_], bh2_);                            \
        }                                                                       \
    }                                                                           \
} while (0)

    GLOAD(0);
    SSTORE(0);
    __syncthreads();
    for (int c = 0; c < nc; c++) {
        if (c + 1 < nc) GLOAD(c + 1);
        COMPUTE(c & 1);
        if (c + 1 < nc) SSTORE((c + 1) & 1);
        __syncthreads();
    }

#pragma unroll
    for (int mi = 0; mi < 2; mi++) {
        const int r0 = bRow + wm * 32 + mi * 16 + (lane >> 2);
#pragma unroll
        for (int ni = 0; ni < 8; ni++) {
            const int col = bCol + wn * 64 + ni * 8 + (lane & 3) * 2;
            const float b0 = bias[col], b1 = bias[col + 1];
            if (r0 < M) {
                float c0 = acc[mi][ni][0] + b0, c1 = acc[mi][ni][1] + b1;
                if (RELU) { c0 = fmaxf(c0, 0.f); c1 = fmaxf(c1, 0.f); }
                *(float2*)(C + (size_t)r0 * N + col) = make_float2(c0, c1);
            }
            if (r0 + 8 < M) {
                float c2 = acc[mi][ni][2] + b0, c3 = acc[mi][ni][3] + b1;
                if (RELU) { c2 = fmaxf(c2, 0.f); c3 = fmaxf(c3, 0.f); }
                *(float2*)(C + (size_t)(r0 + 8) * N + col) = make_float2(c2, c3);
            }
        }
    }
#undef GLOAD
#undef SSTORE
#undef COMPUTE
}

// ---------------- weight prep: W[K][N] fp32 -> Th/Tl [N][K] bf16 ----------------
__global__ void k_wprep(const float* __restrict__ W, __nv_bfloat16* __restrict__ Th,
                        __nv_bfloat16* __restrict__ Tl, int K, int N) {
    __shared__ float s[32][33];
    int n0 = blockIdx.x * 32, k0 = blockIdx.y * 32;
    for (int r = threadIdx.y; r < 32; r += 8)
        s[r][threadIdx.x] = W[(size_t)(k0 + r) * N + n0 + threadIdx.x];
    __syncthreads();
    for (int r = threadIdx.y; r < 32; r += 8) {
        float f = s[threadIdx.x][r];
        __nv_bfloat16 hb = __float2bfloat16(f);
        float hv = __bfloat162float(hb);
        size_t o = (size_t)(n0 + r) * K + k0 + threadIdx.x;
        Th[o] = hb;
        Tl[o] = __float2bfloat16(f - hv);
    }
}

// ---------------- CSR build ----------------
__global__ void k_zeroi(int* __restrict__ p, unsigned n) {
    unsigned i = blockIdx.x * blockDim.x + threadIdx.x;
    if (i < n) p[i] = 0;
}
__global__ void k_count(const int* __restrict__ dst, int* __restrict__ cnt) {
    unsigned e = blockIdx.x * blockDim.x + threadIdx.x;
    if (e >= TT * EE) return;
    int t = e / EE;
    atomicAdd(&cnt[t * NN + dst[e]], 1);
}
__global__ void k_scan(const int* __restrict__ cnt, int* __restrict__ rowptr,
                       int* __restrict__ cursor) {
    int t = blockIdx.x;
    __shared__ int sdata[1024];
    __shared__ int carry_s;
    if (threadIdx.x == 0) carry_s = t * EE;
    __syncthreads();
    for (int c0 = 0; c0 < NN; c0 += 1024) {
        int i = c0 + threadIdx.x;
        int v = (i < NN) ? cnt[t * NN + i] : 0;
        sdata[threadIdx.x] = v;
        __syncthreads();
        for (int off = 1; off < 1024; off <<= 1) {
            int add = (threadIdx.x >= (unsigned)off) ? sdata[threadIdx.x - off] : 0;
            __syncthreads();
            sdata[threadIdx.x] += add;
            __syncthreads();
        }
        int excl = sdata[threadIdx.x] - v;
        if (i < NN) {
            int r = carry_s + excl;
            rowptr[t * NN + i] = r;
            cursor[t * NN + i] = r;
        }
        __syncthreads();
        if (threadIdx.x == 0) carry_s += sdata[1023];
        __syncthreads();
    }
}
__global__ void k_fill(const int* __restrict__ src, const int* __restrict__ dst,
                       int* __restrict__ cursor, int* __restrict__ eidx) {
    unsigned e = blockIdx.x * blockDim.x + threadIdx.x;
    if (e >= TT * EE) return;
    int t = e / EE;
    int pos = atomicAdd(&cursor[t * NN + dst[e]], 1);
    eidx[pos] = t * NN + src[e];
}
// CSR mean-aggregate: warp per node row; F = F4PL*128 floats
template<int F4PL>
__global__ void k_agg(const float* __restrict__ x, const int* __restrict__ rowptr,
                      const int* __restrict__ cnt, const int* __restrict__ eidx,
                      float* __restrict__ agg) {
    int w = threadIdx.x >> 5, lane = threadIdx.x & 31;
    unsigned n = blockIdx.x * 8 + w;
    if (n >= MB) return;
    const int F = F4PL * 128;
    int beg = rowptr[n], c = cnt[n];
    float4 acc[F4PL];
#pragma unroll
    for (int j = 0; j < F4PL; j++) acc[j] = make_float4(0.f, 0.f, 0.f, 0.f);
    int i = 0;
    for (; i + 1 < c; i += 2) {
        int s0 = eidx[beg + i], s1 = eidx[beg + i + 1];
        const float4* r0 = (const float4*)(x + (size_t)s0 * F);
        const float4* r1 = (const float4*)(x + (size_t)s1 * F);
#pragma unroll
        for (int j = 0; j < F4PL; j++) {
            float4 a = r0[lane + 32 * j], b = r1[lane + 32 * j];
            acc[j].x += a.x + b.x; acc[j].y += a.y + b.y;
            acc[j].z += a.z + b.z; acc[j].w += a.w + b.w;
        }
    }
    if (i < c) {
        const float4* r0 = (const float4*)(x + (size_t)eidx[beg + i] * F);
#pragma unroll
        for (int j = 0; j < F4PL; j++) {
            float4 a = r0[lane + 32 * j];
            acc[j].x += a.x; acc[j].y += a.y; acc[j].z += a.z; acc[j].w += a.w;
        }
    }
    float sc = 1.0f / (float)(c > 0 ? c : 1);
    float4* dst = (float4*)(agg + (size_t)n * F);
#pragma unroll
    for (int j = 0; j < F4PL; j++) {
        acc[j].x *= sc; acc[j].y *= sc; acc[j].z *= sc; acc[j].w *= sc;
        dst[lane + 32 * j] = acc[j];
    }
}

// ---------------- misc kernels ----------------
__global__ void k_normgather(const float* __restrict__ h2, const int* __restrict__ idx,
                             float* __restrict__ att_out, float* __restrict__ hbuf, int off) {
    int w = threadIdx.x >> 5, lane = threadIdx.x & 31;
    unsigned tp = blockIdx.x * 8 + w;
    int t = tp >> 12, p = tp & 4095;
    int n = idx[t * PP + p];
    const float* row = h2 + ((size_t)t * NN + n) * HH;
    float v[8]; float ss = 0.f;
#pragma unroll
    for (int i = 0; i < 8; i++) { v[i] = row[lane + i * 32]; ss += v[i] * v[i]; }
#pragma unroll
    for (int o = 16; o; o >>= 1) ss += __shfl_xor_sync(0xffffffffu, ss, o);
    float inv = 1.0f / fmaxf(sqrtf(ss), 1e-12f);
    size_t o0 = (size_t)tp * DDm + off;
#pragma unroll
    for (int i = 0; i < 8; i++) {
        float val = v[i] * inv;
        att_out[o0 + lane + i * 32] = val;
        hbuf[o0 + lane + i * 32] = val;
    }
}
__global__ void k_attn(const float* __restrict__ qkv) {
    int p = blockIdx.x, h = blockIdx.y;
    int tid = threadIdx.x;
    __shared__ float qs[TT][64], ks[TT][64], vs[TT][64];
    __shared__ float att[TT][4];
    size_t base = (size_t)p * 1536 + h * 64 + tid;
#pragma unroll
    for (int t = 0; t < TT; t++) {
        size_t off = (size_t)t * PP * 1536 + base;
        qs[t][tid] = qkv[off];
        ks[t][tid] = qkv[off + 512];
        vs[t][tid] = qkv[off + 1024];
    }
    __syncthreads();
    {
        int t = tid >> 2, j = tid & 3, s = t - j;
        float sc = -INFINITY;
        if (s >= 0) {
            float a = 0.f;
#pragma unroll
            for (int d = 0; d < 64; d++) a += qs[t][d] * ks[s][d];
            sc = a * 0.125f;
        }
        att[t][j] = sc;
    }
    __syncthreads();
    if (tid < TT) {
        float m = -INFINITY;
#pragma unroll
        for (int j = 0; j < 4; j++) m = fmaxf(m, att[tid][j]);
        float sum = 0.f, e[4];
#pragma unroll
        for (int j = 0; j < 4; j++) {
            float x = att[tid][j];
            float ee = (x == -INFINITY) ? 0.f : expf(x - m);
            e[j] = ee; sum += ee;
        }
        float inv = 1.0f / sum;
#pragma unroll
        for (int j = 0; j < 4; j++) att[tid][j] = e[j] * inv;
    }
    __syncthreads();
    size_t obase = (size_t)p * DDm + h * 64 + tid;
#pragma unroll
    for (int t = 0; t < TT; t++) {
        float a = 0.f;
#pragma unroll
        for (int j = 0; j < 4; j++) {
            int s = t - j;
            if (s >= 0) a += att[t][j] * vs[s][tid];
        }
        g_o[(size_t)t * PP * DDm + obase] = a;
    }
}
__global__ void k_ln(const float* __restrict__ r, const float* __restrict__ g,
                     const float* __restrict__ b) {
    int w = threadIdx.x >> 5, lane = threadIdx.x & 31;
    size_t row = (size_t)blockIdx.x * 8 + w;
    float* xr = g_h + row * DDm;
    const float* rr = r + row * DDm;
    float v[16]; float s = 0.f;
#pragma unroll
    for (int i = 0; i < 16; i++) {
        int c = lane + i * 32;
        float t = xr[c] + rr[c];
        v[i] = t; s += t;
    }
#pragma unroll
    for (int o = 16; o; o >>= 1) s += __shfl_xor_sync(0xffffffffu, s, o);
    float mean = s * (1.0f / DDm);
    float vs = 0.f;
#pragma unroll
    for (int i = 0; i < 16; i++) { float d = v[i] - mean; vs += d * d; }
#pragma unroll
    for (int o = 16; o; o >>= 1) vs += __shfl_xor_sync(0xffffffffu, vs, o);
    float inv = rsqrtf(vs * (1.0f / DDm) + 1e-5f);
#pragma unroll
    for (int i = 0; i < 16; i++) {
        int c = lane + i * 32;
        xr[c] = (v[i] - mean) * inv * g[c] + b[c];
    }
}
__global__ void k_out(const float* __restrict__ wout, float* __restrict__ out) {
    int w = threadIdx.x >> 5, lane = threadIdx.x & 31;
    size_t row = (size_t)blockIdx.x * 8 + w;
    const float* hr = g_h + row * DDm;
    float s = 0.f;
#pragma unroll
    for (int i = 0; i < 16; i++) { int c = lane + i * 32; s += hr[c] * wout[c]; }
#pragma unroll
    for (int o = 16; o; o >>= 1) s += __shfl_xor_sync(0xffffffffu, s, o);
    if (lane == 0) out[row] = s;
}

// =======================================================================================
extern "C" void kernel_launch(void* const* d_in, const int* in_sizes, int n_in,
                              void* d_out, int out_size) {
    const float* x_i  = (const float*)d_in[0];
    const float* x_j  = (const float*)d_in[1];
    const int* src_i  = (const int*)d_in[2];
    const int* dst_i  = (const int*)d_in[3];
    const int* src_j  = (const int*)d_in[4];
    const int* dst_j  = (const int*)d_in[5];
    const int* idx_i  = (const int*)d_in[6];
    const int* idx_j  = (const int*)d_in[7];
    const float* W1s  = (const float*)d_in[8];
    const float* W1n  = (const float*)d_in[9];
    const float* b1   = (const float*)d_in[10];
    const float* W2s  = (const float*)d_in[11];
    const float* W2n  = (const float*)d_in[12];
    const float* b2   = (const float*)d_in[13];
    const float* Wq   = (const float*)d_in[14];
    const float* Wk   = (const float*)d_in[15];
    const float* Wv   = (const float*)d_in[16];
    const float* bq   = (const float*)d_in[17];
    const float* bk   = (const float*)d_in[18];
    const float* bv   = (const float*)d_in[19];
    const float* Wo   = (const float*)d_in[20];
    const float* bo   = (const float*)d_in[21];
    const float* Wf1  = (const float*)d_in[22];
    const float* bf1  = (const float*)d_in[23];
    const float* Wf2  = (const float*)d_in[24];
    const float* bf2  = (const float*)d_in[25];
    const float* g1   = (const float*)d_in[26];
    const float* bg1  = (const float*)d_in[27];
    const float* g2   = (const float*)d_in[28];
    const float* bg2  = (const float*)d_in[29];
    const float* Wout = (const float*)d_in[30];
    float* out = (float*)d_out;

    float *p_aggB, *p_h1B, *p_h2B, *p_h, *p_qkv, *p_o, *p_proj, *p_ff, *p_bqkv;
    int *p_cnt, *p_rowptr, *p_cursor, *p_eidx;
    __nv_bfloat16* p_w;
    cudaGetSymbolAddress((void**)&p_cnt,    g_cnt);
    cudaGetSymbolAddress((void**)&p_rowptr, g_rowptr);
    cudaGetSymbolAddress((void**)&p_cursor, g_cursor);
    cudaGetSymbolAddress((void**)&p_eidx,   g_eidx);
    cudaGetSymbolAddress((void**)&p_aggB,   g_aggB);
    cudaGetSymbolAddress((void**)&p_h1B,    g_h1B);
    cudaGetSymbolAddress((void**)&p_h2B,    g_h2B);
    cudaGetSymbolAddress((void**)&p_h,      g_h);
    cudaGetSymbolAddress((void**)&p_qkv,    g_qkv);
    cudaGetSymbolAddress((void**)&p_o,      g_o);
    cudaGetSymbolAddress((void**)&p_proj,   g_proj);
    cudaGetSymbolAddress((void**)&p_ff,     g_ff);
    cudaGetSymbolAddress((void**)&p_bqkv,   g_bqkv);
    cudaGetSymbolAddress((void**)&p_w,      g_w);

    cudaFuncSetAttribute(gemm_mma<false>, cudaFuncAttributeMaxDynamicSharedMemorySize, GSMEM);
    cudaFuncSetAttribute(gemm_mma<true>,  cudaFuncAttributeMaxDynamicSharedMemorySize, GSMEM);

    // ---- stream fork (capture-safe: event fork off the capturing default stream) ----
    cudaStream_t s1;
    cudaStreamCreate(&s1);
    cudaEvent_t evF, evW, evJ;
    cudaEventCreateWithFlags(&evF, cudaEventDisableTiming);
    cudaEventCreateWithFlags(&evW, cudaEventDisableTiming);
    cudaEventCreateWithFlags(&evJ, cudaEventDisableTiming);
    cudaEventRecord(evF, 0);
    cudaStreamWaitEvent(s1, evF, 0);

    // ---- weight prep on default stream ----
    size_t off = 0;
    auto prep = [&](const float* W, int K, int N) -> size_t {
        size_t b = off;
        k_wprep<<<dim3(N/32, K/32), dim3(32, 8)>>>(W, p_w + b, p_w + b + (size_t)K*N, K, N);
        off += 2 * (size_t)K * N;
        return b;
    };
    size_t oW1s = prep(W1s, DIN, HH), oW1n = prep(W1n, DIN, HH);
    size_t oW2s = prep(W2s, HH, HH),  oW2n = prep(W2n, HH, HH);
    // SAGE weights done — record for s1's GEMMs
    cudaEventRecord(evW, 0);

    size_t oQKV[2];
    for (int l = 0; l < 2; l++) {
        size_t b = off; off += 2 * (size_t)1536 * DDm;
        const size_t KN = (size_t)DDm * DDm, LO = (size_t)1536 * DDm;
        k_wprep<<<dim3(DDm/32, DDm/32), dim3(32, 8)>>>(Wq + (size_t)l*KN, p_w + b,        p_w + b + LO,        DDm, DDm);
        k_wprep<<<dim3(DDm/32, DDm/32), dim3(32, 8)>>>(Wk + (size_t)l*KN, p_w + b + KN,   p_w + b + LO + KN,   DDm, DDm);
        k_wprep<<<dim3(DDm/32, DDm/32), dim3(32, 8)>>>(Wv + (size_t)l*KN, p_w + b + 2*KN, p_w + b + LO + 2*KN, DDm, DDm);
        oQKV[l] = b;
    }
    size_t oWo[2], oWf1[2], oWf2[2];
    for (int l = 0; l < 2; l++) {
        oWo[l]  = prep(Wo  + (size_t)l*DDm*DDm, DDm, DDm);
        oWf1[l] = prep(Wf1 + (size_t)l*DDm*FFD, DDm, FFD);
        oWf2[l] = prep(Wf2 + (size_t)l*FFD*DDm, FFD, DDm);
    }
    auto BH = [&](size_t b) { return p_w + b; };
    auto BL = [&](size_t b, size_t K, size_t N) { return p_w + b + K * N; };

    for (int l = 0; l < 2; l++) {
        cudaMemcpyAsync(p_bqkv + l*1536,        bq + l*DDm, DDm*4, cudaMemcpyDeviceToDevice);
        cudaMemcpyAsync(p_bqkv + l*1536 + 512,  bk + l*DDm, DDm*4, cudaMemcpyDeviceToDevice);
        cudaMemcpyAsync(p_bqkv + l*1536 + 1024, bv + l*DDm, DDm*4, cudaMemcpyDeviceToDevice);
    }

    // ---------- GraphSAGE: two independent graph pipelines on two streams ----------
    for (int gsel = 0; gsel < 2; gsel++) {
        cudaStream_t st = gsel ? s1 : (cudaStream_t)0;
        const float* x  = gsel ? x_j   : x_i;
        const int* src  = gsel ? src_j : src_i;
        const int* dstp = gsel ? dst_j : dst_i;
        const int* idx  = gsel ? idx_j : idx_i;
        int*   cnt    = p_cnt    + (size_t)gsel * MB;
        int*   rowptr = p_rowptr + (size_t)gsel * MB;
        int*   cursor = p_cursor + (size_t)gsel * MB;
        int*   eidx   = p_eidx   + (size_t)gsel * TT * EE;
        float* aggB   = p_aggB   + (size_t)gsel * MB * HH;
        float* h1B    = p_h1B    + (size_t)gsel * MB * HH;
        float* h2B    = p_h2B    + (size_t)gsel * MB * HH;

        // CSR build + layer-1 aggregation (no weights needed)
        k_zeroi<<<(MB + 255)/256, 256, 0, st>>>(cnt, MB);
        k_count<<<(TT*EE + 255)/256, 256, 0, st>>>(dstp, cnt);
        k_scan <<<TT, 1024, 0, st>>>(cnt, rowptr, cursor);
        k_fill <<<(TT*EE + 255)/256, 256, 0, st>>>(src, dstp, cursor, eidx);
        k_agg<1><<<(MB + 7)/8, 256, 0, st>>>(x, rowptr, cnt, eidx, aggB);

        if (gsel == 1) cudaStreamWaitEvent(st, evW, 0);  // SAGE weights ready

        gemm_mma<true><<<dim3(HH/128, (MB + 127)/128), 256, GSMEM, st>>>(
            x, BH(oW1s), BL(oW1s, DIN, HH), DIN,
            aggB, BH(oW1n), BL(oW1n, DIN, HH), DIN, b1, h1B, MB, HH);

        k_agg<2><<<(MB + 7)/8, 256, 0, st>>>(h1B, rowptr, cnt, eidx, aggB);
        gemm_mma<false><<<dim3(HH/128, (MB + 127)/128), 256, GSMEM, st>>>(
            h1B, BH(oW2s), BL(oW2s, HH, HH), HH,
            aggB, BH(oW2n), BL(oW2n, HH, HH), HH, b2, h2B, MB, HH);

        k_normgather<<<TPR/8, 256, 0, st>>>(h2B, idx, out, p_h, gsel * HH);
    }
    // join s1 back into the default stream before the transformer
    cudaEventRecord(evJ, s1);
    cudaStreamWaitEvent(0, evJ, 0);

    // ---------- transformer (L=2) ----------
    for (int l = 0; l < 2; l++) {
        gemm_mma<false><<<dim3(1536/128, TPR/128), 256, GSMEM>>>(
            p_h, BH(oQKV[l]), BL(oQKV[l], 1536, DDm), DDm,
            nullptr, nullptr, nullptr, 0, p_bqkv + l*1536, p_qkv, TPR, 1536);

        k_attn<<<dim3(PP, 8), 64>>>(p_qkv);

        gemm_mma<false><<<dim3(DDm/128, TPR/128), 256, GSMEM>>>(
            p_o, BH(oWo[l]), BL(oWo[l], DDm, DDm), DDm,
            nullptr, nullptr, nullptr, 0, bo + l*DDm, p_proj, TPR, DDm);
        k_ln<<<TPR/8, 256>>>(p_proj, g1 + l*DDm, bg1 + l*DDm);

        gemm_mma<true><<<dim3(FFD/128, TPR/128), 256, GSMEM>>>(
            p_h, BH(oWf1[l]), BL(oWf1[l], DDm, FFD), DDm,
            nullptr, nullptr, nullptr, 0, bf1 + l*FFD, p_ff, TPR, FFD);
        gemm_mma<false><<<dim3(DDm/128, TPR/128), 256, GSMEM>>>(
            p_ff, BH(oWf2[l]), BL(oWf2[l], FFD, DDm), FFD,
            nullptr, nullptr, nullptr, 0, bf2 + l*DDm, p_proj, TPR, DDm);
        k_ln<<<TPR/8, 256>>>(p_proj, g2 + l*DDm, bg2 + l*DDm);
    }

    k_out<<<TPR/8, 256>>>(Wout, out + (size_t)TPR * DDm);
}

// round 8
// speedup vs baseline: 3.5118x; 1.2128x over previous
#include <cuda_runtime.h>
#include <cuda_fp16.h>
#include <math.h>
#include <stdint.h>

#define NN   20000
#define EE   320000
#define TT   16
#define PP   4096
#define DIN  128
#define HH   256
#define DDm  512
#define FFD  2048
#define TPR  (TT*PP)   // 65536
#define MB   (TT*NN)   // 320000 batched rows

// ---------------- scratch (static device globals; no allocation) ----------------
__device__ int   g_cnt   [2*MB];
__device__ int   g_rowptr[2*MB];
__device__ int   g_cursor[2*MB];
__device__ int   g_eidx  [2*TT*EE];
__device__ float g_aggB[(size_t)2*MB*HH];
__device__ float g_h1B [(size_t)2*MB*HH];
__device__ float g_h2B [(size_t)2*MB*HH];
__device__ float g_h   [(size_t)TPR*DDm];
__device__ float g_qkv [(size_t)TPR*1536];
__device__ float g_o   [(size_t)TPR*DDm];
__device__ float g_proj[(size_t)TPR*DDm];
__device__ float g_ff  [(size_t)TPR*FFD];
__device__ float g_bqkv[2*1536];
__device__ __half g_w[6488064];

// ---------------- helpers ----------------
__device__ __forceinline__ uint32_t smem_u32(const void* p) {
    uint32_t a;
    asm("{ .reg .u64 t; cvta.to.shared.u64 t, %1; cvt.u32.u64 %0, t; }" : "=r"(a) : "l"(p));
    return a;
}
__device__ __forceinline__ void ldsm4(uint32_t* r, uint32_t addr) {
    asm volatile("ldmatrix.sync.aligned.m8n8.x4.shared.b16 {%0,%1,%2,%3}, [%4];"
                 : "=r"(r[0]), "=r"(r[1]), "=r"(r[2]), "=r"(r[3]) : "r"(addr));
}
__device__ __forceinline__ void mma16816(float* c, const uint32_t* a, const uint32_t* b) {
    asm volatile("mma.sync.aligned.m16n8k16.row.col.f32.f16.f16.f32 "
                 "{%0,%1,%2,%3}, {%4,%5,%6,%7}, {%8,%9}, {%0,%1,%2,%3};"
                 : "+f"(c[0]), "+f"(c[1]), "+f"(c[2]), "+f"(c[3])
                 : "r"(a[0]), "r"(a[1]), "r"(a[2]), "r"(a[3]), "r"(b[0]), "r"(b[1]));
}
__device__ __forceinline__ uint32_t packh2(float a, float b) {
    __half2 t = __floats2half2_rn(a, b);
    return *reinterpret_cast<uint32_t*>(&t);
}

// smem geometry: rows of 32 fp16 padded to 80 bytes (conflict-free ldmatrix)
#define RSTR  80
#define MATB  (128*RSTR)
#define BUFB  (3*MATB)     // Ah, Al, Bh
#define GSMEM (2*BUFB)     // double buffered = 61440

// ---------------- HMMA GEMM: C = A1@W1 (+ A2@W2) + bias, opt ReLU ------
// A fp32 [M][K] split on the fly to fp16 hi+lo; W pre-converted fp16 [N][K].
// Two products: Ah*B + Al*B, fp32 accum. Product error ~2^-11 (B rounding).
template<bool RELU>
__global__ void __launch_bounds__(256)
gemm_mma(const float* __restrict__ A1, const __half* __restrict__ B1h, int K1,
         const float* __restrict__ A2, const __half* __restrict__ B2h, int K2,
         const float* __restrict__ bias, float* __restrict__ C, int M, int N) {
    extern __shared__ char smb[];
    const uint32_t sb = smem_u32(smb);
    const int tid = threadIdx.x, lane = tid & 31, wid = tid >> 5;
    const int bRow = blockIdx.y * 128, bCol = blockIdx.x * 128;
    const int wm = wid & 3, wn = wid >> 2;
    const int lrow = tid >> 1, lhalf = tid & 1;

    const int nc1 = K1 >> 5;
    const int nc  = nc1 + (K2 >> 5);

    float acc[2][8][4];
#pragma unroll
    for (int i = 0; i < 2; i++)
#pragma unroll
        for (int j = 0; j < 8; j++)
#pragma unroll
            for (int q = 0; q < 4; q++) acc[i][j][q] = 0.f;

    float a_st[16];
    uint4 bh_st[2];

#define GLOAD(cc) do {                                                          \
    const float* A_; const __half* Bh_; int K_, k0_;                            \
    if ((cc) < nc1) { A_ = A1; Bh_ = B1h; K_ = K1; k0_ = (cc) << 5; }           \
    else { A_ = A2; Bh_ = B2h; K_ = K2; k0_ = ((cc) - nc1) << 5; }              \
    const int grow_ = bRow + lrow;                                              \
    if (grow_ < M) {                                                            \
        const float* ap_ = A_ + (size_t)grow_ * K_ + k0_ + lhalf * 16;          \
        *(float4*)(a_st + 0)  = ((const float4*)ap_)[0];                        \
        *(float4*)(a_st + 4)  = ((const float4*)ap_)[1];                        \
        *(float4*)(a_st + 8)  = ((const float4*)ap_)[2];                        \
        *(float4*)(a_st + 12) = ((const float4*)ap_)[3];                        \
    } else {                                                                    \
        _Pragma("unroll") for (int j_ = 0; j_ < 16; j_++) a_st[j_] = 0.f;       \
    }                                                                           \
    const size_t bo_ = (size_t)(bCol + lrow) * K_ + k0_ + lhalf * 16;           \
    bh_st[0] = ((const uint4*)(Bh_ + bo_))[0];                                  \
    bh_st[1] = ((const uint4*)(Bh_ + bo_))[1];                                  \
} while (0)

#define SSTORE(buf) do {                                                        \
    char* base_ = smb + (buf) * BUFB;                                          \
    const uint32_t ro_ = lrow * RSTR + lhalf * 32;                              \
    uint32_t hi_[8], lo_[8];                                                    \
    _Pragma("unroll") for (int j_ = 0; j_ < 8; j_++) {                          \
        float f0_ = a_st[2*j_], f1_ = a_st[2*j_+1];                             \
        __half h0_ = __float2half_rn(f0_), h1_ = __float2half_rn(f1_);          \
        float v0_ = __half2float(h0_), v1_ = __half2float(h1_);                 \
        hi_[j_] = packh2(v0_, v1_);                                             \
        lo_[j_] = packh2(f0_ - v0_, f1_ - v1_);                                 \
    }                                                                           \
    *(uint4*)(base_ + ro_)             = make_uint4(hi_[0],hi_[1],hi_[2],hi_[3]);\
    *(uint4*)(base_ + ro_ + 16)        = make_uint4(hi_[4],hi_[5],hi_[6],hi_[7]);\
    *(uint4*)(base_ + MATB + ro_)      = make_uint4(lo_[0],lo_[1],lo_[2],lo_[3]);\
    *(uint4*)(base_ + MATB + ro_ + 16) = make_uint4(lo_[4],lo_[5],lo_[6],lo_[7]);\
    *(uint4*)(base_ + 2*MATB + ro_)      = bh_st[0];                            \
    *(uint4*)(base_ + 2*MATB + ro_ + 16) = bh_st[1];                            \
} while (0)

#define COMPUTE(buf) do {                                                       \
    const uint32_t ah_ = sb + (buf) * BUFB;                                     \
    const uint32_t al_ = ah_ + MATB, bhp_ = ah_ + 2*MATB;                       \
    _Pragma("unroll") for (int ks_ = 0; ks_ < 2; ks_++) {                       \
        uint32_t aH_[2][4], aL_[2][4], bH_[4][4];                               \
        const int arow_ = wm * 32 + (lane & 15);                                \
        const int acol_ = ks_ * 32 + ((lane >> 4) << 4);                        \
        ldsm4(aH_[0], ah_ + arow_ * RSTR + acol_);                              \
        ldsm4(aH_[1], ah_ + (arow_ + 16) * RSTR + acol_);                       \
        ldsm4(aL_[0], al_ + arow_ * RSTR + acol_);                              \
        ldsm4(aL_[1], al_ + (arow_ + 16) * RSTR + acol_);                       \
        const int br_ = lane & 7, bg_ = lane >> 3;                              \
        const int brow_ = wn * 64 + ((bg_ >> 1) << 3) + br_;                    \
        const int bcol_ = ks_ * 32 + ((bg_ & 1) << 4);                          \
        _Pragma("unroll") for (int nj_ = 0; nj_ < 4; nj_++) {                   \
            ldsm4(bH_[nj_], bhp_ + (brow_ + nj_ * 16) * RSTR + bcol_);          \
        }                                                                       \
        _Pragma("unroll") for (int mi_ = 0; mi_ < 2; mi_++)                     \
        _Pragma("unroll") for (int ni_ = 0; ni_ < 8; ni_++) {                   \
            const uint32_t* bh2_ = &bH_[ni_ >> 1][(ni_ & 1) * 2];               \
            mma16816(acc[mi_][ni_], aH_[mi_], bh2_);                            \
            mma16816(acc[mi_][ni_], aL_[mi_], bh2_);                            \
        }                                                                       \
    }                                                                           \
} while (0)

    GLOAD(0);
    SSTORE(0);
    __syncthreads();
    for (int c = 0; c < nc; c++) {
        if (c + 1 < nc) GLOAD(c + 1);
        COMPUTE(c & 1);
        if (c + 1 < nc) SSTORE((c + 1) & 1);
        __syncthreads();
    }

#pragma unroll
    for (int mi = 0; mi < 2; mi++) {
        const int r0 = bRow + wm * 32 + mi * 16 + (lane >> 2);
#pragma unroll
        for (int ni = 0; ni < 8; ni++) {
            const int col = bCol + wn * 64 + ni * 8 + (lane & 3) * 2;
            const float b0 = bias[col], b1 = bias[col + 1];
            if (r0 < M) {
                float c0 = acc[mi][ni][0] + b0, c1 = acc[mi][ni][1] + b1;
                if (RELU) { c0 = fmaxf(c0, 0.f); c1 = fmaxf(c1, 0.f); }
                *(float2*)(C + (size_t)r0 * N + col) = make_float2(c0, c1);
            }
            if (r0 + 8 < M) {
                float c2 = acc[mi][ni][2] + b0, c3 = acc[mi][ni][3] + b1;
                if (RELU) { c2 = fmaxf(c2, 0.f); c3 = fmaxf(c3, 0.f); }
                *(float2*)(C + (size_t)(r0 + 8) * N + col) = make_float2(c2, c3);
            }
        }
    }
#undef GLOAD
#undef SSTORE
#undef COMPUTE
}

// ---------------- weight prep: W[K][N] fp32 -> T [N][K] fp16 ----------------
__global__ void k_wprep(const float* __restrict__ W, __half* __restrict__ Th,
                        int K, int N) {
    __shared__ float s[32][33];
    int n0 = blockIdx.x * 32, k0 = blockIdx.y * 32;
    for (int r = threadIdx.y; r < 32; r += 8)
        s[r][threadIdx.x] = W[(size_t)(k0 + r) * N + n0 + threadIdx.x];
    __syncthreads();
    for (int r = threadIdx.y; r < 32; r += 8) {
        float f = s[threadIdx.x][r];
        Th[(size_t)(n0 + r) * K + k0 + threadIdx.x] = __float2half_rn(f);
    }
}

// ---------------- CSR build ----------------
__global__ void k_zeroi(int* __restrict__ p, unsigned n) {
    unsigned i = blockIdx.x * blockDim.x + threadIdx.x;
    if (i < n) p[i] = 0;
}
__global__ void k_count(const int* __restrict__ dst, int* __restrict__ cnt) {
    unsigned e = blockIdx.x * blockDim.x + threadIdx.x;
    if (e >= TT * EE) return;
    int t = e / EE;
    atomicAdd(&cnt[t * NN + dst[e]], 1);
}
__global__ void k_scan(const int* __restrict__ cnt, int* __restrict__ rowptr,
                       int* __restrict__ cursor) {
    int t = blockIdx.x;
    __shared__ int sdata[1024];
    __shared__ int carry_s;
    if (threadIdx.x == 0) carry_s = t * EE;
    __syncthreads();
    for (int c0 = 0; c0 < NN; c0 += 1024) {
        int i = c0 + threadIdx.x;
        int v = (i < NN) ? cnt[t * NN + i] : 0;
        sdata[threadIdx.x] = v;
        __syncthreads();
        for (int off = 1; off < 1024; off <<= 1) {
            int add = (threadIdx.x >= (unsigned)off) ? sdata[threadIdx.x - off] : 0;
            __syncthreads();
            sdata[threadIdx.x] += add;
            __syncthreads();
        }
        int excl = sdata[threadIdx.x] - v;
        if (i < NN) {
            int r = carry_s + excl;
            rowptr[t * NN + i] = r;
            cursor[t * NN + i] = r;
        }
        __syncthreads();
        if (threadIdx.x == 0) carry_s += sdata[1023];
        __syncthreads();
    }
}
__global__ void k_fill(const int* __restrict__ src, const int* __restrict__ dst,
                       int* __restrict__ cursor, int* __restrict__ eidx) {
    unsigned e = blockIdx.x * blockDim.x + threadIdx.x;
    if (e >= TT * EE) return;
    int t = e / EE;
    int pos = atomicAdd(&cursor[t * NN + dst[e]], 1);
    eidx[pos] = t * NN + src[e];
}
// CSR mean-aggregate: warp per node row; F = F4PL*128 floats
template<int F4PL>
__global__ void k_agg(const float* __restrict__ x, const int* __restrict__ rowptr,
                      const int* __restrict__ cnt, const int* __restrict__ eidx,
                      float* __restrict__ agg) {
    int w = threadIdx.x >> 5, lane = threadIdx.x & 31;
    unsigned n = blockIdx.x * 8 + w;
    if (n >= MB) return;
    const int F = F4PL * 128;
    int beg = rowptr[n], c = cnt[n];
    float4 acc[F4PL];
#pragma unroll
    for (int j = 0; j < F4PL; j++) acc[j] = make_float4(0.f, 0.f, 0.f, 0.f);
    int i = 0;
    for (; i + 1 < c; i += 2) {
        int s0 = eidx[beg + i], s1 = eidx[beg + i + 1];
        const float4* r0 = (const float4*)(x + (size_t)s0 * F);
        const float4* r1 = (const float4*)(x + (size_t)s1 * F);
#pragma unroll
        for (int j = 0; j < F4PL; j++) {
            float4 a = r0[lane + 32 * j], b = r1[lane + 32 * j];
            acc[j].x += a.x + b.x; acc[j].y += a.y + b.y;
            acc[j].z += a.z + b.z; acc[j].w += a.w + b.w;
        }
    }
    if (i < c) {
        const float4* r0 = (const float4*)(x + (size_t)eidx[beg + i] * F);
#pragma unroll
        for (int j = 0; j < F4PL; j++) {
            float4 a = r0[lane + 32 * j];
            acc[j].x += a.x; acc[j].y += a.y; acc[j].z += a.z; acc[j].w += a.w;
        }
    }
    float sc = 1.0f / (float)(c > 0 ? c : 1);
    float4* dst = (float4*)(agg + (size_t)n * F);
#pragma unroll
    for (int j = 0; j < F4PL; j++) {
        acc[j].x *= sc; acc[j].y *= sc; acc[j].z *= sc; acc[j].w *= sc;
        dst[lane + 32 * j] = acc[j];
    }
}

// ---------------- misc kernels ----------------
__global__ void k_normgather(const float* __restrict__ h2, const int* __restrict__ idx,
                             float* __restrict__ att_out, float* __restrict__ hbuf, int off) {
    int w = threadIdx.x >> 5, lane = threadIdx.x & 31;
    unsigned tp = blockIdx.x * 8 + w;
    int t = tp >> 12, p = tp & 4095;
    int n = idx[t * PP + p];
    const float* row = h2 + ((size_t)t * NN + n) * HH;
    float v[8]; float ss = 0.f;
#pragma unroll
    for (int i = 0; i < 8; i++) { v[i] = row[lane + i * 32]; ss += v[i] * v[i]; }
#pragma unroll
    for (int o = 16; o; o >>= 1) ss += __shfl_xor_sync(0xffffffffu, ss, o);
    float inv = 1.0f / fmaxf(sqrtf(ss), 1e-12f);
    size_t o0 = (size_t)tp * DDm + off;
#pragma unroll
    for (int i = 0; i < 8; i++) {
        float val = v[i] * inv;
        att_out[o0 + lane + i * 32] = val;
        hbuf[o0 + lane + i * 32] = val;
    }
}
__global__ void k_attn(const float* __restrict__ qkv) {
    int p = blockIdx.x, h = blockIdx.y;
    int tid = threadIdx.x;
    __shared__ float qs[TT][64], ks[TT][64], vs[TT][64];
    __shared__ float att[TT][4];
    size_t base = (size_t)p * 1536 + h * 64 + tid;
#pragma unroll
    for (int t = 0; t < TT; t++) {
        size_t off = (size_t)t * PP * 1536 + base;
        qs[t][tid] = qkv[off];
        ks[t][tid] = qkv[off + 512];
        vs[t][tid] = qkv[off + 1024];
    }
    __syncthreads();
    {
        int t = tid >> 2, j = tid & 3, s = t - j;
        float sc = -INFINITY;
        if (s >= 0) {
            float a = 0.f;
#pragma unroll
            for (int d = 0; d < 64; d++) a += qs[t][d] * ks[s][d];
            sc = a * 0.125f;
        }
        att[t][j] = sc;
    }
    __syncthreads();
    if (tid < TT) {
        float m = -INFINITY;
#pragma unroll
        for (int j = 0; j < 4; j++) m = fmaxf(m, att[tid][j]);
        float sum = 0.f, e[4];
#pragma unroll
        for (int j = 0; j < 4; j++) {
            float x = att[tid][j];
            float ee = (x == -INFINITY) ? 0.f : expf(x - m);
            e[j] = ee; sum += ee;
        }
        float inv = 1.0f / sum;
#pragma unroll
        for (int j = 0; j < 4; j++) att[tid][j] = e[j] * inv;
    }
    __syncthreads();
    size_t obase = (size_t)p * DDm + h * 64 + tid;
#pragma unroll
    for (int t = 0; t < TT; t++) {
        float a = 0.f;
#pragma unroll
        for (int j = 0; j < 4; j++) {
            int s = t - j;
            if (s >= 0) a += att[t][j] * vs[s][tid];
        }
        g_o[(size_t)t * PP * DDm + obase] = a;
    }
}
__global__ void k_ln(const float* __restrict__ r, const float* __restrict__ g,
                     const float* __restrict__ b) {
    int w = threadIdx.x >> 5, lane = threadIdx.x & 31;
    size_t row = (size_t)blockIdx.x * 8 + w;
    float* xr = g_h + row * DDm;
    const float* rr = r + row * DDm;
    float v[16]; float s = 0.f;
#pragma unroll
    for (int i = 0; i < 16; i++) {
        int c = lane + i * 32;
        float t = xr[c] + rr[c];
        v[i] = t; s += t;
    }
#pragma unroll
    for (int o = 16; o; o >>= 1) s += __shfl_xor_sync(0xffffffffu, s, o);
    float mean = s * (1.0f / DDm);
    float vs = 0.f;
#pragma unroll
    for (int i = 0; i < 16; i++) { float d = v[i] - mean; vs += d * d; }
#pragma unroll
    for (int o = 16; o; o >>= 1) vs += __shfl_xor_sync(0xffffffffu, vs, o);
    float inv = rsqrtf(vs * (1.0f / DDm) + 1e-5f);
#pragma unroll
    for (int i = 0; i < 16; i++) {
        int c = lane + i * 32;
        xr[c] = (v[i] - mean) * inv * g[c] + b[c];
    }
}
__global__ void k_out(const float* __restrict__ wout, float* __restrict__ out) {
    int w = threadIdx.x >> 5, lane = threadIdx.x & 31;
    size_t row = (size_t)blockIdx.x * 8 + w;
    const float* hr = g_h + row * DDm;
    float s = 0.f;
#pragma unroll
    for (int i = 0; i < 16; i++) { int c = lane + i * 32; s += hr[c] * wout[c]; }
#pragma unroll
    for (int o = 16; o; o >>= 1) s += __shfl_xor_sync(0xffffffffu, s, o);
    if (lane == 0) out[row] = s;
}

// =======================================================================================
extern "C" void kernel_launch(void* const* d_in, const int* in_sizes, int n_in,
                              void* d_out, int out_size) {
    const float* x_i  = (const float*)d_in[0];
    const float* x_j  = (const float*)d_in[1];
    const int* src_i  = (const int*)d_in[2];
    const int* dst_i  = (const int*)d_in[3];
    const int* src_j  = (const int*)d_in[4];
    const int* dst_j  = (const int*)d_in[5];
    const int* idx_i  = (const int*)d_in[6];
    const int* idx_j  = (const int*)d_in[7];
    const float* W1s  = (const float*)d_in[8];
    const float* W1n  = (const float*)d_in[9];
    const float* b1   = (const float*)d_in[10];
    const float* W2s  = (const float*)d_in[11];
    const float* W2n  = (const float*)d_in[12];
    const float* b2   = (const float*)d_in[13];
    const float* Wq   = (const float*)d_in[14];
    const float* Wk   = (const float*)d_in[15];
    const float* Wv   = (const float*)d_in[16];
    const float* bq   = (const float*)d_in[17];
    const float* bk   = (const float*)d_in[18];
    const float* bv   = (const float*)d_in[19];
    const float* Wo   = (const float*)d_in[20];
    const float* bo   = (const float*)d_in[21];
    const float* Wf1  = (const float*)d_in[22];
    const float* bf1  = (const float*)d_in[23];
    const float* Wf2  = (const float*)d_in[24];
    const float* bf2  = (const float*)d_in[25];
    const float* g1   = (const float*)d_in[26];
    const float* bg1  = (const float*)d_in[27];
    const float* g2   = (const float*)d_in[28];
    const float* bg2  = (const float*)d_in[29];
    const float* Wout = (const float*)d_in[30];
    float* out = (float*)d_out;

    float *p_aggB, *p_h1B, *p_h2B, *p_h, *p_qkv, *p_o, *p_proj, *p_ff, *p_bqkv;
    int *p_cnt, *p_rowptr, *p_cursor, *p_eidx;
    __half* p_w;
    cudaGetSymbolAddress((void**)&p_cnt,    g_cnt);
    cudaGetSymbolAddress((void**)&p_rowptr, g_rowptr);
    cudaGetSymbolAddress((void**)&p_cursor, g_cursor);
    cudaGetSymbolAddress((void**)&p_eidx,   g_eidx);
    cudaGetSymbolAddress((void**)&p_aggB,   g_aggB);
    cudaGetSymbolAddress((void**)&p_h1B,    g_h1B);
    cudaGetSymbolAddress((void**)&p_h2B,    g_h2B);
    cudaGetSymbolAddress((void**)&p_h,      g_h);
    cudaGetSymbolAddress((void**)&p_qkv,    g_qkv);
    cudaGetSymbolAddress((void**)&p_o,      g_o);
    cudaGetSymbolAddress((void**)&p_proj,   g_proj);
    cudaGetSymbolAddress((void**)&p_ff,     g_ff);
    cudaGetSymbolAddress((void**)&p_bqkv,   g_bqkv);
    cudaGetSymbolAddress((void**)&p_w,      g_w);

    cudaFuncSetAttribute(gemm_mma<false>, cudaFuncAttributeMaxDynamicSharedMemorySize, GSMEM);
    cudaFuncSetAttribute(gemm_mma<true>,  cudaFuncAttributeMaxDynamicSharedMemorySize, GSMEM);

    // ---- stream fork (capture-safe: event fork off the capturing default stream) ----
    cudaStream_t s1;
    cudaStreamCreate(&s1);
    cudaEvent_t evF, evW, evJ;
    cudaEventCreateWithFlags(&evF, cudaEventDisableTiming);
    cudaEventCreateWithFlags(&evW, cudaEventDisableTiming);
    cudaEventCreateWithFlags(&evJ, cudaEventDisableTiming);
    cudaEventRecord(evF, 0);
    cudaStreamWaitEvent(s1, evF, 0);

    // ---- weight prep on default stream ----
    size_t off = 0;
    auto prep = [&](const float* W, int K, int N) -> size_t {
        size_t b = off;
        k_wprep<<<dim3(N/32, K/32), dim3(32, 8)>>>(W, p_w + b, K, N);
        off += (size_t)K * N;
        return b;
    };
    size_t oW1s = prep(W1s, DIN, HH), oW1n = prep(W1n, DIN, HH);
    size_t oW2s = prep(W2s, HH, HH),  oW2n = prep(W2n, HH, HH);
    cudaEventRecord(evW, 0);   // SAGE weights ready

    size_t oQKV[2];
    for (int l = 0; l < 2; l++) {
        size_t b = off; off += (size_t)1536 * DDm;
        const size_t KN = (size_t)DDm * DDm;
        k_wprep<<<dim3(DDm/32, DDm/32), dim3(32, 8)>>>(Wq + (size_t)l*KN, p_w + b,        DDm, DDm);
        k_wprep<<<dim3(DDm/32, DDm/32), dim3(32, 8)>>>(Wk + (size_t)l*KN, p_w + b + KN,   DDm, DDm);
        k_wprep<<<dim3(DDm/32, DDm/32), dim3(32, 8)>>>(Wv + (size_t)l*KN, p_w + b + 2*KN, DDm, DDm);
        oQKV[l] = b;
    }
    size_t oWo[2], oWf1[2], oWf2[2];
    for (int l = 0; l < 2; l++) {
        oWo[l]  = prep(Wo  + (size_t)l*DDm*DDm, DDm, DDm);
        oWf1[l] = prep(Wf1 + (size_t)l*DDm*FFD, DDm, FFD);
        oWf2[l] = prep(Wf2 + (size_t)l*FFD*DDm, FFD, DDm);
    }
    auto BH = [&](size_t b) { return p_w + b; };

    for (int l = 0; l < 2; l++) {
        cudaMemcpyAsync(p_bqkv + l*1536,        bq + l*DDm, DDm*4, cudaMemcpyDeviceToDevice);
        cudaMemcpyAsync(p_bqkv + l*1536 + 512,  bk + l*DDm, DDm*4, cudaMemcpyDeviceToDevice);
        cudaMemcpyAsync(p_bqkv + l*1536 + 1024, bv + l*DDm, DDm*4, cudaMemcpyDeviceToDevice);
    }

    // ---------- GraphSAGE: two independent graph pipelines on two streams ----------
    for (int gsel = 0; gsel < 2; gsel++) {
        cudaStream_t st = gsel ? s1 : (cudaStream_t)0;
        const float* x  = gsel ? x_j   : x_i;
        const int* src  = gsel ? src_j : src_i;
        const int* dstp = gsel ? dst_j : dst_i;
        const int* idx  = gsel ? idx_j : idx_i;
        int*   cnt    = p_cnt    + (size_t)gsel * MB;
        int*   rowptr = p_rowptr + (size_t)gsel * MB;
        int*   cursor = p_cursor + (size_t)gsel * MB;
        int*   eidx   = p_eidx   + (size_t)gsel * TT * EE;
        float* aggB   = p_aggB   + (size_t)gsel * MB * HH;
        float* h1B    = p_h1B    + (size_t)gsel * MB * HH;
        float* h2B    = p_h2B    + (size_t)gsel * MB * HH;

        k_zeroi<<<(MB + 255)/256, 256, 0, st>>>(cnt, MB);
        k_count<<<(TT*EE + 255)/256, 256, 0, st>>>(dstp, cnt);
        k_scan <<<TT, 1024, 0, st>>>(cnt, rowptr, cursor);
        k_fill <<<(TT*EE + 255)/256, 256, 0, st>>>(src, dstp, cursor, eidx);
        k_agg<1><<<(MB + 7)/8, 256, 0, st>>>(x, rowptr, cnt, eidx, aggB);

        if (gsel == 1) cudaStreamWaitEvent(st, evW, 0);

        gemm_mma<true><<<dim3(HH/128, (MB + 127)/128), 256, GSMEM, st>>>(
            x, BH(oW1s), DIN, aggB, BH(oW1n), DIN, b1, h1B, MB, HH);

        k_agg<2><<<(MB + 7)/8, 256, 0, st>>>(h1B, rowptr, cnt, eidx, aggB);
        gemm_mma<false><<<dim3(HH/128, (MB + 127)/128), 256, GSMEM, st>>>(
            h1B, BH(oW2s), HH, aggB, BH(oW2n), HH, b2, h2B, MB, HH);

        k_normgather<<<TPR/8, 256, 0, st>>>(h2B, idx, out, p_h, gsel * HH);
    }
    cudaEventRecord(evJ, s1);
    cudaStreamWaitEvent(0, evJ, 0);

    // ---------- transformer (L=2) ----------
    for (int l = 0; l < 2; l++) {
        gemm_mma<false><<<dim3(1536/128, TPR/128), 256, GSMEM>>>(
            p_h, BH(oQKV[l]), DDm, nullptr, nullptr, 0,
            p_bqkv + l*1536, p_qkv, TPR, 1536);

        k_attn<<<dim3(PP, 8), 64>>>(p_qkv);

        gemm_mma<false><<<dim3(DDm/128, TPR/128), 256, GSMEM>>>(
            p_o, BH(oWo[l]), DDm, nullptr, nullptr, 0,
            bo + l*DDm, p_proj, TPR, DDm);
        k_ln<<<TPR/8, 256>>>(p_proj, g1 + l*DDm, bg1 + l*DDm);

        gemm_mma<true><<<dim3(FFD/128, TPR/128), 256, GSMEM>>>(
            p_h, BH(oWf1[l]), DDm, nullptr, nullptr, 0,
            bf1 + l*FFD, p_ff, TPR, FFD);
        gemm_mma<false><<<dim3(DDm/128, TPR/128), 256, GSMEM>>>(
            p_ff, BH(oWf2[l]), FFD, nullptr, nullptr, 0,
            bf2 + l*DDm, p_proj, TPR, DDm);
        k_ln<<<TPR/8, 256>>>(p_proj, g2 + l*DDm, bg2 + l*DDm);
    }

    k_out<<<TPR/8, 256>>>(Wout, out + (size_t)TPR * DDm);
}